// round 12
// baseline (speedup 1.0000x reference)
#include <cuda_runtime.h>
#include <cuda_fp16.h>
#include <cstdint>

#define BDIM 4096
#define DDIM 768
#define FDIM 6144
#define CDIM 1000
#define KSEL 64

// ---- mma-GEMM tiling (R8-proven): 128x128 CTA tile, 256 threads ---------------
#define KC2 32
#define NCH (DDIM / KC2)          // 24
#define ROWBYTES 80               // 32 fp16 (64B) + 16B pad: conflict-free ldmatrix
#define TILEB (128 * ROWBYTES)    // 10240 B
#define BUFB (4 * TILEB)          // Ah, Am, Bh, Bm = 40960
#define SMEMDYN (2 * BUFB)        // 81920 B

#define MAXFLAG 4096
#define CAND_MAX 64
#define GAP_TAU 2e-5f

// top-k candidate machinery
#define CANDN 256
#define BREAK_CNT 160

// fused split kernel partition
#define BT_BLOCKS ((FDIM / 32) * (DDIM / 32))   // 4608
#define A_BLOCKS 1024

// ---- scratch ------------------------------------------------------------------
__device__ float g_h[(size_t)BDIM * FDIM];
__device__ float g_vals[BDIM * KSEL];
__device__ int   g_idx [BDIM * KSEL];
__device__ unsigned g_T[BDIM];
__device__ unsigned g_nflag;
__device__ int   g_flagrows[MAXFLAG];
__device__ __half gAh[(size_t)BDIM * DDIM];
__device__ __half gAm[(size_t)BDIM * DDIM];
__device__ __half gBh[(size_t)FDIM * DDIM];   // W_inter^T limbs, [n][k]
__device__ __half gBm[(size_t)FDIM * DDIM];

// ---- helpers -------------------------------------------------------------------
__device__ __forceinline__ uint32_t smem_u32(const void* p) {
    uint32_t a;
    asm("{ .reg .u64 t; cvta.to.shared.u64 t, %1; cvt.u32.u64 %0, t; }" : "=r"(a) : "l"(p));
    return a;
}
__device__ __forceinline__ void cp_async16(uint32_t dst, const void* src) {
    asm volatile("cp.async.cg.shared.global [%0], [%1], 16;" :: "r"(dst), "l"(src));
}
__device__ __forceinline__ void ldsm4(uint32_t* r, uint32_t addr) {
    asm volatile("ldmatrix.sync.aligned.m8n8.x4.shared.b16 {%0,%1,%2,%3}, [%4];"
                 : "=r"(r[0]), "=r"(r[1]), "=r"(r[2]), "=r"(r[3]) : "r"(addr));
}
__device__ __forceinline__ void mma16816(float* d, const uint32_t* a, const uint32_t* b) {
    asm volatile("mma.sync.aligned.m16n8k16.row.col.f32.f16.f16.f32 "
                 "{%0,%1,%2,%3}, {%4,%5,%6,%7}, {%8,%9}, {%0,%1,%2,%3};"
                 : "+f"(d[0]), "+f"(d[1]), "+f"(d[2]), "+f"(d[3])
                 : "r"(a[0]), "r"(a[1]), "r"(a[2]), "r"(a[3]), "r"(b[0]), "r"(b[1]));
}

// ---- fused split kernel: exact 2-limb fp16 decomposition of A and W^T ------------
__global__ void __launch_bounds__(256) split_fused(const float* __restrict__ x,
                                                   const float* __restrict__ W)
{
    if (blockIdx.x == 0 && threadIdx.x == 0) g_nflag = 0;

    if (blockIdx.x < BT_BLOCKS) {
        // ---- W^T limbs (32x32 transpose tile)
        __shared__ float t[32][33];
        const int bid = blockIdx.x;
        const int n0 = (bid % (FDIM / 32)) * 32;
        const int k0 = (bid / (FDIM / 32)) * 32;
        const int tx = threadIdx.x & 31, ty = threadIdx.x >> 5;
#pragma unroll
        for (int i = 0; i < 32; i += 8)
            t[ty + i][tx] = W[(size_t)(k0 + ty + i) * FDIM + n0 + tx];
        __syncthreads();
#pragma unroll
        for (int i = 0; i < 32; i += 8) {
            float v = t[tx][ty + i];
            __half h = __float2half_rn(v);
            float r1 = v - __half2float(h);
            size_t o = (size_t)(n0 + ty + i) * DDIM + k0 + tx;
            gBh[o] = h; gBm[o] = __float2half_rn(r1);
        }
    } else {
        // ---- A limbs (contiguous chunks)
        const size_t n = (size_t)BDIM * DDIM;
        const unsigned aid = blockIdx.x - BT_BLOCKS;
        for (size_t i = (size_t)aid * 256 + threadIdx.x; i < n;
             i += (size_t)A_BLOCKS * 256) {
            float v = x[i];
            __half h = __float2half_rn(v);
            float r1 = v - __half2float(h);
            gAh[i] = h; gAm[i] = __float2half_rn(r1);
        }
    }
}

// ---- tensor-core GEMM: h = relu(x @ W + b), fp16x3 -------------------------------
__device__ __forceinline__ void load_tiles(uint32_t sbase, int buf, int ch,
                                           int bm, int bn, int tid)
{
    const uint32_t bb = sbase + buf * BUFB;
    const int k0 = ch * KC2;
    const __half* srcs[4] = { gAh, gAm, gBh, gBm };
#pragma unroll
    for (int t = 0; t < 4; t++) {
        const int rbase = (t < 2) ? bm : bn;
        const __half* sp = srcs[t] + (size_t)rbase * DDIM + k0;
        const uint32_t tb = bb + t * TILEB;
#pragma unroll
        for (int i = tid; i < 512; i += 256) {
            const int row = i >> 2, seg = i & 3;
            cp_async16(tb + row * ROWBYTES + seg * 16, sp + (size_t)row * DDIM + seg * 8);
        }
    }
    asm volatile("cp.async.commit_group;" ::: "memory");
}

__global__ void __launch_bounds__(256, 2) mma_gemm(const float* __restrict__ bias)
{
    extern __shared__ char dsm[];
    const uint32_t sbase = smem_u32(dsm);
    const int tid = threadIdx.x, wid = tid >> 5, lane = tid & 31;
    const int bm = blockIdx.y * 128, bn = blockIdx.x * 128;
    const int wm = (wid >> 2) * 64;
    const int wn = (wid & 3) * 32;

    float d[4][4][4];
#pragma unroll
    for (int i = 0; i < 4; i++)
#pragma unroll
        for (int j = 0; j < 4; j++)
#pragma unroll
            for (int q = 0; q < 4; q++) d[i][j][q] = 0.f;

    load_tiles(sbase, 0, 0, bm, bn, tid);
    load_tiles(sbase, 1, 1, bm, bn, tid);

    const uint32_t aoff = (uint32_t)(wm + (lane & 15)) * ROWBYTES + ((lane >> 4) * 8) * 2;
    const uint32_t boff = (uint32_t)(wn + ((lane >> 4) & 1) * 8 + (lane & 7)) * ROWBYTES
                        + (((lane >> 3) & 1) * 8) * 2;

#pragma unroll 1
    for (int ch = 0; ch < NCH; ch++) {
        const int buf = ch & 1;
        if (ch < NCH - 1) asm volatile("cp.async.wait_group 1;" ::: "memory");
        else              asm volatile("cp.async.wait_group 0;" ::: "memory");
        __syncthreads();

        const uint32_t bb = sbase + buf * BUFB;
#pragma unroll
        for (int kk = 0; kk < 2; kk++) {
            const uint32_t ko = kk * 32;
            uint32_t ah[4][4], am[4][4], bh[2][4], bmm[2][4];
#pragma unroll
            for (int ma = 0; ma < 4; ma++) {
                ldsm4(ah[ma], bb + 0 * TILEB + aoff + ma * 16 * ROWBYTES + ko);
                ldsm4(am[ma], bb + 1 * TILEB + aoff + ma * 16 * ROWBYTES + ko);
            }
#pragma unroll
            for (int pr = 0; pr < 2; pr++) {
                ldsm4(bh[pr],  bb + 2 * TILEB + boff + pr * 16 * ROWBYTES + ko);
                ldsm4(bmm[pr], bb + 3 * TILEB + boff + pr * 16 * ROWBYTES + ko);
            }
#pragma unroll
            for (int ma = 0; ma < 4; ma++)
#pragma unroll
                for (int na = 0; na < 4; na++) {
                    const uint32_t* bhf = &bh[na >> 1][(na & 1) * 2];
                    const uint32_t* bmf = &bmm[na >> 1][(na & 1) * 2];
                    mma16816(d[ma][na], ah[ma], bhf);   // h*h
                    mma16816(d[ma][na], ah[ma], bmf);   // h*m
                    mma16816(d[ma][na], am[ma], bhf);   // m*h
                }
        }
        __syncthreads();
        if (ch + 2 < NCH) load_tiles(sbase, buf, ch + 2, bm, bn, tid);
    }

#pragma unroll
    for (int na = 0; na < 4; na++) {
        const int n0g = bn + wn + na * 8 + (lane & 3) * 2;
        const float b0 = bias[n0g], b1 = bias[n0g + 1];
#pragma unroll
        for (int ma = 0; ma < 4; ma++) {
            const int m0g = bm + wm + ma * 16 + (lane >> 2);
            float v0 = __fadd_rn(d[ma][na][0], b0);
            float v1 = __fadd_rn(d[ma][na][1], b1);
            float v2 = __fadd_rn(d[ma][na][2], b0);
            float v3 = __fadd_rn(d[ma][na][3], b1);
            float2 o0 = { (v0 > 0.f) ? v0 : 0.f, (v1 > 0.f) ? v1 : 0.f };
            float2 o1 = { (v2 > 0.f) ? v2 : 0.f, (v3 > 0.f) ? v3 : 0.f };
            *(float2*)&g_h[(size_t)m0g * FDIM + n0g]       = o0;
            *(float2*)&g_h[(size_t)(m0g + 8) * FDIM + n0g] = o1;
        }
    }
}

// ---- top-64: truncated bitwise search + exact candidate ranking -------------------
__global__ void __launch_bounds__(256) topk_kernel(float* __restrict__ sparse)
{
    const int row = blockIdx.x;
    const int tid = threadIdx.x;
    const int lane = tid & 31, wid = tid >> 5;

    __shared__ unsigned warpcnt[2][8];
    __shared__ unsigned warpmax[8];
    __shared__ unsigned cu[CANDN];
    __shared__ int      ci[CANDN];
    __shared__ unsigned s_T64, s_v65;

    const float* hrow = g_h + (size_t)row * FDIM;
    uint4 vb[6];
#pragma unroll
    for (int q = 0; q < 6; q++)
        vb[q] = ((const uint4*)hrow)[q * 256 + tid];

    if (tid == 0) { s_T64 = 0u; s_v65 = 0u; }

    // ---- phase 1: truncated greedy bit search
    unsigned T = 0, curcnt = FDIM;
#pragma unroll 1
    for (int b = 30; b >= 0; --b) {
        const unsigned cand = T | (1u << b);
        unsigned lc = 0;
#pragma unroll
        for (int q = 0; q < 6; q++) {
            lc += (vb[q].x >= cand) + (vb[q].y >= cand)
                + (vb[q].z >= cand) + (vb[q].w >= cand);
        }
        lc = __reduce_add_sync(0xFFFFFFFFu, lc);
        const int pb = b & 1;
        if (lane == 0) warpcnt[pb][wid] = lc;
        __syncthreads();
        unsigned cnt = 0;
#pragma unroll
        for (int w = 0; w < 8; w++) cnt += warpcnt[pb][w];
        if (cnt >= KSEL) { T = cand; curcnt = cnt; }
        if (curcnt <= BREAK_CNT) break;
    }
    __syncthreads();

    // ---- phase 2: atomic-free ballot compaction of candidates {u >= T}
    unsigned wcnt = 0;
#pragma unroll
    for (int q = 0; q < 6; q++) {
        unsigned u[4] = { vb[q].x, vb[q].y, vb[q].z, vb[q].w };
#pragma unroll
        for (int c = 0; c < 4; c++)
            wcnt += __popc(__ballot_sync(0xFFFFFFFFu, u[c] >= T));
    }
    if (lane == 0) warpcnt[0][wid] = wcnt;
    __syncthreads();
    unsigned nc = 0, wbase = 0;
#pragma unroll
    for (int w = 0; w < 8; w++) {
        if (w < wid) wbase += warpcnt[0][w];
        nc += warpcnt[0][w];
    }
    if (nc > CANDN) nc = CANDN;
    {
        unsigned base = wbase;
        const unsigned ltmask = (1u << lane) - 1u;
#pragma unroll
        for (int q = 0; q < 6; q++) {
            const int c0 = q * 1024 + tid * 4;
            unsigned u[4] = { vb[q].x, vb[q].y, vb[q].z, vb[q].w };
#pragma unroll
            for (int c = 0; c < 4; c++) {
                const bool pred = (u[c] >= T);
                const unsigned m = __ballot_sync(0xFFFFFFFFu, pred);
                if (pred) {
                    unsigned slot = base + __popc(m & ltmask);
                    if (slot < CANDN) { cu[slot] = u[c]; ci[slot] = c0 + c; }
                }
                base += __popc(m);
            }
        }
    }
    __syncthreads();

    // ---- phase 3: exact rank (value desc, index asc) over candidates
    float* vrow = g_vals + row * KSEL;
    int*   irow = g_idx  + row * KSEL;
    for (unsigned j = tid; j < nc; j += 256) {
        const unsigned v = cu[j];
        const int id = ci[j];
        int r = 0;
        for (unsigned m = 0; m < nc; m++) {
            const unsigned w = cu[m];
            r += (w > v) || (w == v && ci[m] < id);
        }
        if (r < KSEL) { vrow[r] = __uint_as_float(v); irow[r] = id; }
        if (r == KSEL - 1) s_T64 = v;
        if (r == KSEL)     s_v65 = v;
    }
    __syncthreads();
    const unsigned T64 = s_T64;

    // ---- phase 4: write sparse, track non-candidate max
    float* srow = sparse + (size_t)row * FDIM;
    unsigned bmax = 0;
#pragma unroll
    for (int q = 0; q < 6; q++) {
        const int c0 = q * 1024 + tid * 4;
        unsigned u[4] = { vb[q].x, vb[q].y, vb[q].z, vb[q].w };
        float o[4];
#pragma unroll
        for (int c = 0; c < 4; c++) {
            o[c] = (u[c] > T64) ? __uint_as_float(u[c]) : 0.f;
            if (u[c] < T) bmax = max(bmax, u[c]);
        }
        *(float4*)&srow[c0] = *(const float4*)o;
    }
#pragma unroll
    for (int o2 = 16; o2; o2 >>= 1) bmax = max(bmax, __shfl_xor_sync(0xFFFFFFFFu, bmax, o2));
    if (lane == 0) warpmax[wid] = bmax;
    __syncthreads();

    if (tid < KSEL) srow[irow[tid]] = vrow[tid];

    if (tid == 0) {
        unsigned below;
        if (nc > KSEL) below = s_v65;
        else {
            below = 0;
#pragma unroll
            for (int w = 0; w < 8; w++) below = max(below, warpmax[w]);
        }
        g_T[row] = T64;
        const float gap = __uint_as_float(T64) - __uint_as_float(below);
        if (T64 != 0u && gap < GAP_TAU) {
            unsigned p = atomicAdd(&g_nflag, 1u);
            if (p < MAXFLAG) g_flagrows[p] = row;
        }
    }
}

// ---- exact repair of flagged rows -------------------------------------------------
__global__ void __launch_bounds__(256) repair_kernel(
    const float* __restrict__ x, const float* __restrict__ Wi,
    const float* __restrict__ bi, float* __restrict__ sparse)
{
    __shared__ float xs[DDIM];
    __shared__ int   cand[CAND_MAX];
    __shared__ float cex[CAND_MAX];
    __shared__ float red[256];
    __shared__ unsigned s_nc, s_nhi;

    unsigned nf = min(g_nflag, (unsigned)MAXFLAG);
    if (blockIdx.x >= nf) return;
    const int row = g_flagrows[blockIdx.x];
    const int tid = threadIdx.x;
    const float Tval = __uint_as_float(g_T[row]);
    const float* hrow = g_h + (size_t)row * FDIM;

    for (int i = tid; i < DDIM; i += 256) xs[i] = x[(size_t)row * DDIM + i];
    if (tid == 0) { s_nc = 0; s_nhi = 0; }
    __syncthreads();

    unsigned nhi_loc = 0;
    for (int f = tid; f < FDIM; f += 256) {
        float v = hrow[f];
        if (fabsf(v - Tval) <= GAP_TAU) {
            unsigned p = atomicAdd(&s_nc, 1u);
            if (p < CAND_MAX) cand[p] = f;
        } else if (v > Tval) nhi_loc++;
    }
    atomicAdd(&s_nhi, nhi_loc);
    __syncthreads();
    const unsigned nc = s_nc;
    if (nc > CAND_MAX) return;

    for (unsigned j = 0; j < nc; j++) {
        const int f = cand[j];
        float s = 0.f, c = 0.f;
        for (int d = tid; d < DDIM; d += 256) {
            float p = __fmaf_rn(xs[d], Wi[(size_t)d * FDIM + f], 0.f);
            float y = __fsub_rn(p, c);
            float t2 = __fadd_rn(s, y);
            c = __fsub_rn(__fsub_rn(t2, s), y);
            s = t2;
        }
        red[tid] = s;
        __syncthreads();
        for (int o = 128; o > 0; o >>= 1) {
            if (tid < o) red[tid] = __fadd_rn(red[tid], red[tid + o]);
            __syncthreads();
        }
        if (tid == 0) {
            float v = __fadd_rn(red[0], bi[f]);
            cex[j] = (v > 0.f) ? v : 0.f;
        }
        __syncthreads();
    }
    if (tid != 0) return;

    float* srow = sparse + (size_t)row * FDIM;
    float* vrow = g_vals + row * KSEL;
    int*   irow = g_idx  + row * KSEL;

    int k_rem = KSEL - (int)s_nhi;
    bool want[CAND_MAX], cur[CAND_MAX];
    for (unsigned j = 0; j < nc; j++) {
        want[j] = false;
        cur[j] = (srow[cand[j]] != 0.f);
    }
    for (int slot = 0; slot < k_rem; slot++) {
        int best = -1;
        for (unsigned j = 0; j < nc; j++) {
            if (want[j]) continue;
            if (best < 0 || cex[j] > cex[best] ||
                (cex[j] == cex[best] && cand[j] < cand[best])) best = (int)j;
        }
        if (best >= 0) want[best] = true;
    }
    int addq[CAND_MAX]; int na = 0;
    for (unsigned j = 0; j < nc; j++) if (want[j] && !cur[j]) addq[na++] = (int)j;
    int ai = 0;
    for (unsigned j = 0; j < nc && ai < na; j++) {
        if (cur[j] && !want[j]) {
            int rf = cand[j];
            int af = cand[addq[ai]]; ai++;
            float av = hrow[af];
            srow[rf] = 0.f;
            srow[af] = av;
            for (int q = 0; q < KSEL; q++)
                if (irow[q] == rf) { irow[q] = af; vrow[q] = av; break; }
        }
    }
}

// ---- classifier (fp32 gather — R10-proven) -------------------------------------------
__global__ void __launch_bounds__(256) cls_kernel(
    const float* __restrict__ Wc, const float* __restrict__ bc,
    float* __restrict__ logits)
{
    const int row = blockIdx.x;
    const int tid = threadIdx.x;
    __shared__ float sv[KSEL];
    __shared__ int   si[KSEL];
    if (tid < KSEL) {
        sv[tid] = g_vals[row * KSEL + tid];
        si[tid] = g_idx [row * KSEL + tid];
    }
    __syncthreads();
    if (tid >= 250) return;
    const int c = tid * 4;
    float4 acc = *(const float4*)&bc[c];
#pragma unroll 4
    for (int j = 0; j < KSEL; j++) {
        const float v = sv[j];
        const float4 w = *(const float4*)&Wc[(size_t)si[j] * CDIM + c];
        acc.x = fmaf(v, w.x, acc.x);
        acc.y = fmaf(v, w.y, acc.y);
        acc.z = fmaf(v, w.z, acc.z);
        acc.w = fmaf(v, w.w, acc.w);
    }
    *(float4*)&logits[(size_t)row * CDIM + c] = acc;
}

// ----------------------------------------------------------------------------------------
extern "C" void kernel_launch(void* const* d_in, const int* in_sizes, int n_in,
                              void* d_out, int out_size)
{
    const float* x  = (const float*)d_in[0];
    const float* Wi = (const float*)d_in[1];
    const float* bi = (const float*)d_in[2];
    const float* Wc = (const float*)d_in[3];
    const float* bc = (const float*)d_in[4];
    (void)in_sizes; (void)n_in; (void)out_size;

    float* sparse = (float*)d_out;
    float* logits = (float*)d_out + (size_t)BDIM * FDIM;

    static int smem_set = 0;
    if (!smem_set) {
        cudaFuncSetAttribute(mma_gemm, cudaFuncAttributeMaxDynamicSharedMemorySize, SMEMDYN);
        smem_set = 1;
    }

    split_fused<<<BT_BLOCKS + A_BLOCKS, 256>>>(x, Wi);
    mma_gemm<<<dim3(FDIM / 128, BDIM / 128), 256, SMEMDYN>>>(bi);
    topk_kernel<<<BDIM, 256>>>(sparse);
    repair_kernel<<<MAXFLAG, 256>>>(x, Wi, bi, sparse);
    cls_kernel<<<BDIM, 256>>>(Wc, bc, logits);
}

// round 13
// speedup vs baseline: 1.3647x; 1.3647x over previous
#include <cuda_runtime.h>
#include <cuda_fp16.h>
#include <cstdint>

#define BDIM 4096
#define DDIM 768
#define FDIM 6144
#define CDIM 1000
#define KSEL 64

// ---- mma-GEMM tiling: 128x128 CTA tile, 512 threads (16 warps, 32x32 warp tile)
#define KC2 32
#define NCH (DDIM / KC2)          // 24
#define ROWBYTES 80               // 32 fp16 (64B) + 16B pad: conflict-free ldmatrix
#define TILEB (128 * ROWBYTES)    // 10240 B
#define BUFB (4 * TILEB)          // Ah, Am, Bh, Bm = 40960
#define SMEMDYN (2 * BUFB)        // 81920 B

#define MAXFLAG 4096
#define CAND_MAX 64
#define GAP_TAU 2e-5f

// top-k candidate machinery
#define CANDN 256
#define BREAK_CNT 160

// fused split kernel partition
#define BT_BLOCKS ((FDIM / 32) * (DDIM / 32))   // 4608
#define A_BLOCKS 1024

// ---- scratch ------------------------------------------------------------------
__device__ float g_h[(size_t)BDIM * FDIM];
__device__ float g_vals[BDIM * KSEL];
__device__ int   g_idx [BDIM * KSEL];
__device__ unsigned g_T[BDIM];
__device__ unsigned g_nflag;
__device__ int   g_flagrows[MAXFLAG];
__device__ __half gAh[(size_t)BDIM * DDIM];
__device__ __half gAm[(size_t)BDIM * DDIM];
__device__ __half gBh[(size_t)FDIM * DDIM];   // W_inter^T limbs, [n][k]
__device__ __half gBm[(size_t)FDIM * DDIM];

// ---- helpers -------------------------------------------------------------------
__device__ __forceinline__ uint32_t smem_u32(const void* p) {
    uint32_t a;
    asm("{ .reg .u64 t; cvta.to.shared.u64 t, %1; cvt.u32.u64 %0, t; }" : "=r"(a) : "l"(p));
    return a;
}
__device__ __forceinline__ void cp_async16(uint32_t dst, const void* src) {
    asm volatile("cp.async.cg.shared.global [%0], [%1], 16;" :: "r"(dst), "l"(src));
}
__device__ __forceinline__ void ldsm4(uint32_t* r, uint32_t addr) {
    asm volatile("ldmatrix.sync.aligned.m8n8.x4.shared.b16 {%0,%1,%2,%3}, [%4];"
                 : "=r"(r[0]), "=r"(r[1]), "=r"(r[2]), "=r"(r[3]) : "r"(addr));
}
__device__ __forceinline__ void mma16816(float* d, const uint32_t* a, const uint32_t* b) {
    asm volatile("mma.sync.aligned.m16n8k16.row.col.f32.f16.f16.f32 "
                 "{%0,%1,%2,%3}, {%4,%5,%6,%7}, {%8,%9}, {%0,%1,%2,%3};"
                 : "+f"(d[0]), "+f"(d[1]), "+f"(d[2]), "+f"(d[3])
                 : "r"(a[0]), "r"(a[1]), "r"(a[2]), "r"(a[3]), "r"(b[0]), "r"(b[1]));
}

// ---- fused split kernel: exact 2-limb fp16 decomposition of A and W^T ------------
__global__ void __launch_bounds__(256) split_fused(const float* __restrict__ x,
                                                   const float* __restrict__ W)
{
    if (blockIdx.x == 0 && threadIdx.x == 0) g_nflag = 0;

    if (blockIdx.x < BT_BLOCKS) {
        // ---- W^T limbs (32x32 transpose tile)
        __shared__ float t[32][33];
        const int bid = blockIdx.x;
        const int n0 = (bid % (FDIM / 32)) * 32;
        const int k0 = (bid / (FDIM / 32)) * 32;
        const int tx = threadIdx.x & 31, ty = threadIdx.x >> 5;
#pragma unroll
        for (int i = 0; i < 32; i += 8)
            t[ty + i][tx] = W[(size_t)(k0 + ty + i) * FDIM + n0 + tx];
        __syncthreads();
#pragma unroll
        for (int i = 0; i < 32; i += 8) {
            float v = t[tx][ty + i];
            __half h = __float2half_rn(v);
            float r1 = v - __half2float(h);
            size_t o = (size_t)(n0 + ty + i) * DDIM + k0 + tx;
            gBh[o] = h; gBm[o] = __float2half_rn(r1);
        }
    } else {
        // ---- A limbs (contiguous chunks)
        const size_t n = (size_t)BDIM * DDIM;
        const unsigned aid = blockIdx.x - BT_BLOCKS;
        for (size_t i = (size_t)aid * 256 + threadIdx.x; i < n;
             i += (size_t)A_BLOCKS * 256) {
            float v = x[i];
            __half h = __float2half_rn(v);
            float r1 = v - __half2float(h);
            gAh[i] = h; gAm[i] = __float2half_rn(r1);
        }
    }
}

// ---- tensor-core GEMM: h = relu(x @ W + b), fp16x3, 512 threads ------------------
__device__ __forceinline__ void load_tiles(uint32_t sbase, int buf, int ch,
                                           int bm, int bn, int tid)
{
    const uint32_t bb = sbase + buf * BUFB;
    const int k0 = ch * KC2;
    const __half* srcs[4] = { gAh, gAm, gBh, gBm };
#pragma unroll
    for (int t = 0; t < 4; t++) {
        const int rbase = (t < 2) ? bm : bn;
        const __half* sp = srcs[t] + (size_t)rbase * DDIM + k0;
        const uint32_t tb = bb + t * TILEB;
        // 512 chunks per tile, 512 threads: exactly one each
        const int row = tid >> 2, seg = tid & 3;
        cp_async16(tb + row * ROWBYTES + seg * 16, sp + (size_t)row * DDIM + seg * 8);
    }
    asm volatile("cp.async.commit_group;" ::: "memory");
}

__global__ void __launch_bounds__(512, 1) mma_gemm(const float* __restrict__ bias)
{
    extern __shared__ char dsm[];
    const uint32_t sbase = smem_u32(dsm);
    const int tid = threadIdx.x, wid = tid >> 5, lane = tid & 31;
    const int bm = blockIdx.y * 128, bn = blockIdx.x * 128;
    const int wm = (wid >> 2) * 32;   // 0,32,64,96
    const int wn = (wid & 3) * 32;    // 0..96

    float d[2][4][4];
#pragma unroll
    for (int i = 0; i < 2; i++)
#pragma unroll
        for (int j = 0; j < 4; j++)
#pragma unroll
            for (int q = 0; q < 4; q++) d[i][j][q] = 0.f;

    load_tiles(sbase, 0, 0, bm, bn, tid);
    load_tiles(sbase, 1, 1, bm, bn, tid);

    const uint32_t aoff = (uint32_t)(wm + (lane & 15)) * ROWBYTES + ((lane >> 4) * 8) * 2;
    const uint32_t boff = (uint32_t)(wn + ((lane >> 4) & 1) * 8 + (lane & 7)) * ROWBYTES
                        + (((lane >> 3) & 1) * 8) * 2;

#pragma unroll 1
    for (int ch = 0; ch < NCH; ch++) {
        const int buf = ch & 1;
        if (ch < NCH - 1) asm volatile("cp.async.wait_group 1;" ::: "memory");
        else              asm volatile("cp.async.wait_group 0;" ::: "memory");
        __syncthreads();

        const uint32_t bb = sbase + buf * BUFB;
#pragma unroll
        for (int kk = 0; kk < 2; kk++) {
            const uint32_t ko = kk * 32;
            uint32_t ah[2][4], am[2][4], bh[2][4], bmm[2][4];
#pragma unroll
            for (int ma = 0; ma < 2; ma++) {
                ldsm4(ah[ma], bb + 0 * TILEB + aoff + ma * 16 * ROWBYTES + ko);
                ldsm4(am[ma], bb + 1 * TILEB + aoff + ma * 16 * ROWBYTES + ko);
            }
#pragma unroll
            for (int pr = 0; pr < 2; pr++) {
                ldsm4(bh[pr],  bb + 2 * TILEB + boff + pr * 16 * ROWBYTES + ko);
                ldsm4(bmm[pr], bb + 3 * TILEB + boff + pr * 16 * ROWBYTES + ko);
            }
#pragma unroll
            for (int ma = 0; ma < 2; ma++)
#pragma unroll
                for (int na = 0; na < 4; na++) {
                    const uint32_t* bhf = &bh[na >> 1][(na & 1) * 2];
                    const uint32_t* bmf = &bmm[na >> 1][(na & 1) * 2];
                    mma16816(d[ma][na], ah[ma], bhf);   // h*h
                    mma16816(d[ma][na], ah[ma], bmf);   // h*m
                    mma16816(d[ma][na], am[ma], bhf);   // m*h
                }
        }
        __syncthreads();
        if (ch + 2 < NCH) load_tiles(sbase, buf, ch + 2, bm, bn, tid);
    }

#pragma unroll
    for (int na = 0; na < 4; na++) {
        const int n0g = bn + wn + na * 8 + (lane & 3) * 2;
        const float b0 = bias[n0g], b1 = bias[n0g + 1];
#pragma unroll
        for (int ma = 0; ma < 2; ma++) {
            const int m0g = bm + wm + ma * 16 + (lane >> 2);
            float v0 = __fadd_rn(d[ma][na][0], b0);
            float v1 = __fadd_rn(d[ma][na][1], b1);
            float v2 = __fadd_rn(d[ma][na][2], b0);
            float v3 = __fadd_rn(d[ma][na][3], b1);
            float2 o0 = { (v0 > 0.f) ? v0 : 0.f, (v1 > 0.f) ? v1 : 0.f };
            float2 o1 = { (v2 > 0.f) ? v2 : 0.f, (v3 > 0.f) ? v3 : 0.f };
            *(float2*)&g_h[(size_t)m0g * FDIM + n0g]       = o0;
            *(float2*)&g_h[(size_t)(m0g + 8) * FDIM + n0g] = o1;
        }
    }
}

// ---- top-64: truncated bitwise search + exact candidate ranking -------------------
__global__ void __launch_bounds__(256) topk_kernel(float* __restrict__ sparse)
{
    const int row = blockIdx.x;
    const int tid = threadIdx.x;
    const int lane = tid & 31, wid = tid >> 5;

    __shared__ unsigned warpcnt[2][8];
    __shared__ unsigned warpmax[8];
    __shared__ unsigned cu[CANDN];
    __shared__ int      ci[CANDN];
    __shared__ unsigned s_T64, s_v65;

    const float* hrow = g_h + (size_t)row * FDIM;
    uint4 vb[6];
#pragma unroll
    for (int q = 0; q < 6; q++)
        vb[q] = ((const uint4*)hrow)[q * 256 + tid];

    if (tid == 0) { s_T64 = 0u; s_v65 = 0u; }

    // ---- phase 1: truncated greedy bit search
    unsigned T = 0, curcnt = FDIM;
#pragma unroll 1
    for (int b = 30; b >= 0; --b) {
        const unsigned cand = T | (1u << b);
        unsigned lc = 0;
#pragma unroll
        for (int q = 0; q < 6; q++) {
            lc += (vb[q].x >= cand) + (vb[q].y >= cand)
                + (vb[q].z >= cand) + (vb[q].w >= cand);
        }
        lc = __reduce_add_sync(0xFFFFFFFFu, lc);
        const int pb = b & 1;
        if (lane == 0) warpcnt[pb][wid] = lc;
        __syncthreads();
        unsigned cnt = 0;
#pragma unroll
        for (int w = 0; w < 8; w++) cnt += warpcnt[pb][w];
        if (cnt >= KSEL) { T = cand; curcnt = cnt; }
        if (curcnt <= BREAK_CNT) break;
    }
    __syncthreads();

    // ---- phase 2: atomic-free ballot compaction of candidates {u >= T}
    unsigned wcnt = 0;
#pragma unroll
    for (int q = 0; q < 6; q++) {
        unsigned u[4] = { vb[q].x, vb[q].y, vb[q].z, vb[q].w };
#pragma unroll
        for (int c = 0; c < 4; c++)
            wcnt += __popc(__ballot_sync(0xFFFFFFFFu, u[c] >= T));
    }
    if (lane == 0) warpcnt[0][wid] = wcnt;
    __syncthreads();
    unsigned nc = 0, wbase = 0;
#pragma unroll
    for (int w = 0; w < 8; w++) {
        if (w < wid) wbase += warpcnt[0][w];
        nc += warpcnt[0][w];
    }
    if (nc > CANDN) nc = CANDN;
    {
        unsigned base = wbase;
        const unsigned ltmask = (1u << lane) - 1u;
#pragma unroll
        for (int q = 0; q < 6; q++) {
            const int c0 = q * 1024 + tid * 4;
            unsigned u[4] = { vb[q].x, vb[q].y, vb[q].z, vb[q].w };
#pragma unroll
            for (int c = 0; c < 4; c++) {
                const bool pred = (u[c] >= T);
                const unsigned m = __ballot_sync(0xFFFFFFFFu, pred);
                if (pred) {
                    unsigned slot = base + __popc(m & ltmask);
                    if (slot < CANDN) { cu[slot] = u[c]; ci[slot] = c0 + c; }
                }
                base += __popc(m);
            }
        }
    }
    __syncthreads();

    // ---- phase 3: exact rank (value desc, index asc) over candidates
    float* vrow = g_vals + row * KSEL;
    int*   irow = g_idx  + row * KSEL;
    for (unsigned j = tid; j < nc; j += 256) {
        const unsigned v = cu[j];
        const int id = ci[j];
        int r = 0;
        for (unsigned m = 0; m < nc; m++) {
            const unsigned w = cu[m];
            r += (w > v) || (w == v && ci[m] < id);
        }
        if (r < KSEL) { vrow[r] = __uint_as_float(v); irow[r] = id; }
        if (r == KSEL - 1) s_T64 = v;
        if (r == KSEL)     s_v65 = v;
    }
    __syncthreads();
    const unsigned T64 = s_T64;

    // ---- phase 4: write sparse, track non-candidate max
    float* srow = sparse + (size_t)row * FDIM;
    unsigned bmax = 0;
#pragma unroll
    for (int q = 0; q < 6; q++) {
        const int c0 = q * 1024 + tid * 4;
        unsigned u[4] = { vb[q].x, vb[q].y, vb[q].z, vb[q].w };
        float o[4];
#pragma unroll
        for (int c = 0; c < 4; c++) {
            o[c] = (u[c] > T64) ? __uint_as_float(u[c]) : 0.f;
            if (u[c] < T) bmax = max(bmax, u[c]);
        }
        *(float4*)&srow[c0] = *(const float4*)o;
    }
#pragma unroll
    for (int o2 = 16; o2; o2 >>= 1) bmax = max(bmax, __shfl_xor_sync(0xFFFFFFFFu, bmax, o2));
    if (lane == 0) warpmax[wid] = bmax;
    __syncthreads();

    if (tid < KSEL) srow[irow[tid]] = vrow[tid];

    if (tid == 0) {
        unsigned below;
        if (nc > KSEL) below = s_v65;
        else {
            below = 0;
#pragma unroll
            for (int w = 0; w < 8; w++) below = max(below, warpmax[w]);
        }
        g_T[row] = T64;
        const float gap = __uint_as_float(T64) - __uint_as_float(below);
        if (T64 != 0u && gap < GAP_TAU) {
            unsigned p = atomicAdd(&g_nflag, 1u);
            if (p < MAXFLAG) g_flagrows[p] = row;
        }
    }
}

// ---- exact repair of flagged rows -------------------------------------------------
__global__ void __launch_bounds__(256) repair_kernel(
    const float* __restrict__ x, const float* __restrict__ Wi,
    const float* __restrict__ bi, float* __restrict__ sparse)
{
    __shared__ float xs[DDIM];
    __shared__ int   cand[CAND_MAX];
    __shared__ float cex[CAND_MAX];
    __shared__ float red[256];
    __shared__ unsigned s_nc, s_nhi;

    unsigned nf = min(g_nflag, (unsigned)MAXFLAG);
    if (blockIdx.x >= nf) return;
    const int row = g_flagrows[blockIdx.x];
    const int tid = threadIdx.x;
    const float Tval = __uint_as_float(g_T[row]);
    const float* hrow = g_h + (size_t)row * FDIM;

    for (int i = tid; i < DDIM; i += 256) xs[i] = x[(size_t)row * DDIM + i];
    if (tid == 0) { s_nc = 0; s_nhi = 0; }
    __syncthreads();

    unsigned nhi_loc = 0;
    for (int f = tid; f < FDIM; f += 256) {
        float v = hrow[f];
        if (fabsf(v - Tval) <= GAP_TAU) {
            unsigned p = atomicAdd(&s_nc, 1u);
            if (p < CAND_MAX) cand[p] = f;
        } else if (v > Tval) nhi_loc++;
    }
    atomicAdd(&s_nhi, nhi_loc);
    __syncthreads();
    const unsigned nc = s_nc;
    if (nc > CAND_MAX) return;

    for (unsigned j = 0; j < nc; j++) {
        const int f = cand[j];
        float s = 0.f, c = 0.f;
        for (int d = tid; d < DDIM; d += 256) {
            float p = __fmaf_rn(xs[d], Wi[(size_t)d * FDIM + f], 0.f);
            float y = __fsub_rn(p, c);
            float t2 = __fadd_rn(s, y);
            c = __fsub_rn(__fsub_rn(t2, s), y);
            s = t2;
        }
        red[tid] = s;
        __syncthreads();
        for (int o = 128; o > 0; o >>= 1) {
            if (tid < o) red[tid] = __fadd_rn(red[tid], red[tid + o]);
            __syncthreads();
        }
        if (tid == 0) {
            float v = __fadd_rn(red[0], bi[f]);
            cex[j] = (v > 0.f) ? v : 0.f;
        }
        __syncthreads();
    }
    if (tid != 0) return;

    float* srow = sparse + (size_t)row * FDIM;
    float* vrow = g_vals + row * KSEL;
    int*   irow = g_idx  + row * KSEL;

    int k_rem = KSEL - (int)s_nhi;
    bool want[CAND_MAX], cur[CAND_MAX];
    for (unsigned j = 0; j < nc; j++) {
        want[j] = false;
        cur[j] = (srow[cand[j]] != 0.f);
    }
    for (int slot = 0; slot < k_rem; slot++) {
        int best = -1;
        for (unsigned j = 0; j < nc; j++) {
            if (want[j]) continue;
            if (best < 0 || cex[j] > cex[best] ||
                (cex[j] == cex[best] && cand[j] < cand[best])) best = (int)j;
        }
        if (best >= 0) want[best] = true;
    }
    int addq[CAND_MAX]; int na = 0;
    for (unsigned j = 0; j < nc; j++) if (want[j] && !cur[j]) addq[na++] = (int)j;
    int ai = 0;
    for (unsigned j = 0; j < nc && ai < na; j++) {
        if (cur[j] && !want[j]) {
            int rf = cand[j];
            int af = cand[addq[ai]]; ai++;
            float av = hrow[af];
            srow[rf] = 0.f;
            srow[af] = av;
            for (int q = 0; q < KSEL; q++)
                if (irow[q] == rf) { irow[q] = af; vrow[q] = av; break; }
        }
    }
}

// ---- classifier (fp32 gather — R10-proven) -------------------------------------------
__global__ void __launch_bounds__(256) cls_kernel(
    const float* __restrict__ Wc, const float* __restrict__ bc,
    float* __restrict__ logits)
{
    const int row = blockIdx.x;
    const int tid = threadIdx.x;
    __shared__ float sv[KSEL];
    __shared__ int   si[KSEL];
    if (tid < KSEL) {
        sv[tid] = g_vals[row * KSEL + tid];
        si[tid] = g_idx [row * KSEL + tid];
    }
    __syncthreads();
    if (tid >= 250) return;
    const int c = tid * 4;
    float4 acc = *(const float4*)&bc[c];
#pragma unroll 4
    for (int j = 0; j < KSEL; j++) {
        const float v = sv[j];
        const float4 w = *(const float4*)&Wc[(size_t)si[j] * CDIM + c];
        acc.x = fmaf(v, w.x, acc.x);
        acc.y = fmaf(v, w.y, acc.y);
        acc.z = fmaf(v, w.z, acc.z);
        acc.w = fmaf(v, w.w, acc.w);
    }
    *(float4*)&logits[(size_t)row * CDIM + c] = acc;
}

// ----------------------------------------------------------------------------------------
extern "C" void kernel_launch(void* const* d_in, const int* in_sizes, int n_in,
                              void* d_out, int out_size)
{
    const float* x  = (const float*)d_in[0];
    const float* Wi = (const float*)d_in[1];
    const float* bi = (const float*)d_in[2];
    const float* Wc = (const float*)d_in[3];
    const float* bc = (const float*)d_in[4];
    (void)in_sizes; (void)n_in; (void)out_size;

    float* sparse = (float*)d_out;
    float* logits = (float*)d_out + (size_t)BDIM * FDIM;

    static int smem_set = 0;
    if (!smem_set) {
        cudaFuncSetAttribute(mma_gemm, cudaFuncAttributeMaxDynamicSharedMemorySize, SMEMDYN);
        smem_set = 1;
    }

    split_fused<<<BT_BLOCKS + A_BLOCKS, 256>>>(x, Wi);
    mma_gemm<<<dim3(FDIM / 128, BDIM / 128), 512, SMEMDYN>>>(bi);
    topk_kernel<<<BDIM, 256>>>(sparse);
    repair_kernel<<<MAXFLAG, 256>>>(x, Wi, bi, sparse);
    cls_kernel<<<BDIM, 256>>>(Wc, bc, logits);
}

// round 14
// speedup vs baseline: 1.3874x; 1.0167x over previous
#include <cuda_runtime.h>
#include <cuda_fp16.h>
#include <cstdint>

#define BDIM 4096
#define DDIM 768
#define FDIM 6144
#define CDIM 1000
#define KSEL 64

// ---- mma-GEMM tiling (R10-proven): 128x128 CTA tile, 256 threads, 3-stage pipe --
#define KC2 32
#define NCH (DDIM / KC2)          // 24
#define ROWBYTES 80               // 32 fp16 (64B) + 16B pad: conflict-free ldmatrix
#define TILEB (128 * ROWBYTES)    // 10240 B
#define BUFB (4 * TILEB)          // Ah, Am, Bh, Bm = 40960
#define NSTAGE 3
#define SMEMDYN (NSTAGE * BUFB)   // 122880 B

#define MAXFLAG 4096
#define CAND_MAX 64
#define GAP_TAU 2e-5f

// top-k candidate machinery
#define CANDN 256
#define BREAK_CNT 160

// fused split kernel partition
#define BT_BLOCKS ((FDIM / 32) * (DDIM / 32))   // 4608
#define A_BLOCKS 1024

// ---- scratch ------------------------------------------------------------------
__device__ float g_h[(size_t)BDIM * FDIM];
__device__ float g_vals[BDIM * KSEL];
__device__ int   g_idx [BDIM * KSEL];
__device__ unsigned g_T[BDIM];
__device__ unsigned g_nflag;
__device__ int   g_flagrows[MAXFLAG];
__device__ __half gAh[(size_t)BDIM * DDIM];
__device__ __half gAm[(size_t)BDIM * DDIM];
__device__ __half gBh[(size_t)FDIM * DDIM];   // W_inter^T limbs, [n][k]
__device__ __half gBm[(size_t)FDIM * DDIM];

// ---- helpers -------------------------------------------------------------------
__device__ __forceinline__ uint32_t smem_u32(const void* p) {
    uint32_t a;
    asm("{ .reg .u64 t; cvta.to.shared.u64 t, %1; cvt.u32.u64 %0, t; }" : "=r"(a) : "l"(p));
    return a;
}
__device__ __forceinline__ void cp_async16(uint32_t dst, const void* src) {
    asm volatile("cp.async.cg.shared.global [%0], [%1], 16;" :: "r"(dst), "l"(src));
}
__device__ __forceinline__ void ldsm4(uint32_t* r, uint32_t addr) {
    asm volatile("ldmatrix.sync.aligned.m8n8.x4.shared.b16 {%0,%1,%2,%3}, [%4];"
                 : "=r"(r[0]), "=r"(r[1]), "=r"(r[2]), "=r"(r[3]) : "r"(addr));
}
__device__ __forceinline__ void mma16816(float* d, const uint32_t* a, const uint32_t* b) {
    asm volatile("mma.sync.aligned.m16n8k16.row.col.f32.f16.f16.f32 "
                 "{%0,%1,%2,%3}, {%4,%5,%6,%7}, {%8,%9}, {%0,%1,%2,%3};"
                 : "+f"(d[0]), "+f"(d[1]), "+f"(d[2]), "+f"(d[3])
                 : "r"(a[0]), "r"(a[1]), "r"(a[2]), "r"(a[3]), "r"(b[0]), "r"(b[1]));
}

// ---- fused split kernel: exact 2-limb fp16 decomposition of A and W^T ------------
__global__ void __launch_bounds__(256) split_fused(const float* __restrict__ x,
                                                   const float* __restrict__ W)
{
    if (blockIdx.x == 0 && threadIdx.x == 0) g_nflag = 0;

    if (blockIdx.x < BT_BLOCKS) {
        // ---- W^T limbs (32x32 transpose tile)
        __shared__ float t[32][33];
        const int bid = blockIdx.x;
        const int n0 = (bid % (FDIM / 32)) * 32;
        const int k0 = (bid / (FDIM / 32)) * 32;
        const int tx = threadIdx.x & 31, ty = threadIdx.x >> 5;
#pragma unroll
        for (int i = 0; i < 32; i += 8)
            t[ty + i][tx] = W[(size_t)(k0 + ty + i) * FDIM + n0 + tx];
        __syncthreads();
#pragma unroll
        for (int i = 0; i < 32; i += 8) {
            float v = t[tx][ty + i];
            __half h = __float2half_rn(v);
            float r1 = v - __half2float(h);
            size_t o = (size_t)(n0 + ty + i) * DDIM + k0 + tx;
            gBh[o] = h; gBm[o] = __float2half_rn(r1);
        }
    } else {
        // ---- A limbs (contiguous chunks)
        const size_t n = (size_t)BDIM * DDIM;
        const unsigned aid = blockIdx.x - BT_BLOCKS;
        for (size_t i = (size_t)aid * 256 + threadIdx.x; i < n;
             i += (size_t)A_BLOCKS * 256) {
            float v = x[i];
            __half h = __float2half_rn(v);
            float r1 = v - __half2float(h);
            gAh[i] = h; gAm[i] = __float2half_rn(r1);
        }
    }
}

// ---- tensor-core GEMM: h = relu(x @ W + b), fp16x3, 3-stage pipeline --------------
__device__ __forceinline__ void load_tiles(uint32_t sbase, int buf, int ch,
                                           int bm, int bn, int tid)
{
    const uint32_t bb = sbase + buf * BUFB;
    const int k0 = ch * KC2;
    const __half* srcs[4] = { gAh, gAm, gBh, gBm };
#pragma unroll
    for (int t = 0; t < 4; t++) {
        const int rbase = (t < 2) ? bm : bn;
        const __half* sp = srcs[t] + (size_t)rbase * DDIM + k0;
        const uint32_t tb = bb + t * TILEB;
#pragma unroll
        for (int i = tid; i < 512; i += 256) {
            const int row = i >> 2, seg = i & 3;
            cp_async16(tb + row * ROWBYTES + seg * 16, sp + (size_t)row * DDIM + seg * 8);
        }
    }
    asm volatile("cp.async.commit_group;" ::: "memory");
}

__global__ void __launch_bounds__(256, 1) mma_gemm(const float* __restrict__ bias)
{
    extern __shared__ char dsm[];
    const uint32_t sbase = smem_u32(dsm);
    const int tid = threadIdx.x, wid = tid >> 5, lane = tid & 31;
    const int bm = blockIdx.y * 128, bn = blockIdx.x * 128;
    const int wm = (wid >> 2) * 64;
    const int wn = (wid & 3) * 32;

    float d[4][4][4];
#pragma unroll
    for (int i = 0; i < 4; i++)
#pragma unroll
        for (int j = 0; j < 4; j++)
#pragma unroll
            for (int q = 0; q < 4; q++) d[i][j][q] = 0.f;

    load_tiles(sbase, 0, 0, bm, bn, tid);
    load_tiles(sbase, 1, 1, bm, bn, tid);
    load_tiles(sbase, 2, 2, bm, bn, tid);

    const uint32_t aoff = (uint32_t)(wm + (lane & 15)) * ROWBYTES + ((lane >> 4) * 8) * 2;
    const uint32_t boff = (uint32_t)(wn + ((lane >> 4) & 1) * 8 + (lane & 7)) * ROWBYTES
                        + (((lane >> 3) & 1) * 8) * 2;

    int buf = 0;
#pragma unroll 1
    for (int ch = 0; ch < NCH; ch++) {
        if (ch + 2 < NCH)      asm volatile("cp.async.wait_group 2;" ::: "memory");
        else if (ch + 1 < NCH) asm volatile("cp.async.wait_group 1;" ::: "memory");
        else                   asm volatile("cp.async.wait_group 0;" ::: "memory");
        __syncthreads();

        const uint32_t bb = sbase + buf * BUFB;
#pragma unroll
        for (int kk = 0; kk < 2; kk++) {
            const uint32_t ko = kk * 32;
            uint32_t ah[4][4], am[4][4], bh[2][4], bmm[2][4];
#pragma unroll
            for (int ma = 0; ma < 4; ma++) {
                ldsm4(ah[ma], bb + 0 * TILEB + aoff + ma * 16 * ROWBYTES + ko);
                ldsm4(am[ma], bb + 1 * TILEB + aoff + ma * 16 * ROWBYTES + ko);
            }
#pragma unroll
            for (int pr = 0; pr < 2; pr++) {
                ldsm4(bh[pr],  bb + 2 * TILEB + boff + pr * 16 * ROWBYTES + ko);
                ldsm4(bmm[pr], bb + 3 * TILEB + boff + pr * 16 * ROWBYTES + ko);
            }
#pragma unroll
            for (int ma = 0; ma < 4; ma++)
#pragma unroll
                for (int na = 0; na < 4; na++) {
                    const uint32_t* bhf = &bh[na >> 1][(na & 1) * 2];
                    const uint32_t* bmf = &bmm[na >> 1][(na & 1) * 2];
                    mma16816(d[ma][na], ah[ma], bhf);   // h*h
                    mma16816(d[ma][na], ah[ma], bmf);   // h*m
                    mma16816(d[ma][na], am[ma], bhf);   // m*h
                }
        }
        __syncthreads();
        if (ch + 3 < NCH) load_tiles(sbase, buf, ch + 3, bm, bn, tid);
        buf = (buf == NSTAGE - 1) ? 0 : buf + 1;
    }

#pragma unroll
    for (int na = 0; na < 4; na++) {
        const int n0g = bn + wn + na * 8 + (lane & 3) * 2;
        const float b0 = bias[n0g], b1 = bias[n0g + 1];
#pragma unroll
        for (int ma = 0; ma < 4; ma++) {
            const int m0g = bm + wm + ma * 16 + (lane >> 2);
            float v0 = __fadd_rn(d[ma][na][0], b0);
            float v1 = __fadd_rn(d[ma][na][1], b1);
            float v2 = __fadd_rn(d[ma][na][2], b0);
            float v3 = __fadd_rn(d[ma][na][3], b1);
            float2 o0 = { (v0 > 0.f) ? v0 : 0.f, (v1 > 0.f) ? v1 : 0.f };
            float2 o1 = { (v2 > 0.f) ? v2 : 0.f, (v3 > 0.f) ? v3 : 0.f };
            *(float2*)&g_h[(size_t)m0g * FDIM + n0g]       = o0;
            *(float2*)&g_h[(size_t)(m0g + 8) * FDIM + n0g] = o1;
        }
    }
}

// ---- top-64: truncated bitwise search + exact candidate ranking -------------------
__global__ void __launch_bounds__(256) topk_kernel(float* __restrict__ sparse)
{
    const int row = blockIdx.x;
    const int tid = threadIdx.x;
    const int lane = tid & 31, wid = tid >> 5;

    __shared__ unsigned warpcnt[2][8];
    __shared__ unsigned warpmax[8];
    __shared__ unsigned cu[CANDN];
    __shared__ int      ci[CANDN];
    __shared__ unsigned s_T64, s_v65;

    const float* hrow = g_h + (size_t)row * FDIM;
    uint4 vb[6];
#pragma unroll
    for (int q = 0; q < 6; q++)
        vb[q] = ((const uint4*)hrow)[q * 256 + tid];

    if (tid == 0) { s_T64 = 0u; s_v65 = 0u; }

    // ---- phase 1: truncated greedy bit search
    unsigned T = 0, curcnt = FDIM;
#pragma unroll 1
    for (int b = 30; b >= 0; --b) {
        const unsigned cand = T | (1u << b);
        unsigned lc = 0;
#pragma unroll
        for (int q = 0; q < 6; q++) {
            lc += (vb[q].x >= cand) + (vb[q].y >= cand)
                + (vb[q].z >= cand) + (vb[q].w >= cand);
        }
        lc = __reduce_add_sync(0xFFFFFFFFu, lc);
        const int pb = b & 1;
        if (lane == 0) warpcnt[pb][wid] = lc;
        __syncthreads();
        unsigned cnt = 0;
#pragma unroll
        for (int w = 0; w < 8; w++) cnt += warpcnt[pb][w];
        if (cnt >= KSEL) { T = cand; curcnt = cnt; }
        if (curcnt <= BREAK_CNT) break;
    }
    __syncthreads();

    // ---- phase 2: atomic-free ballot compaction of candidates {u >= T}
    unsigned wcnt = 0;
#pragma unroll
    for (int q = 0; q < 6; q++) {
        unsigned u[4] = { vb[q].x, vb[q].y, vb[q].z, vb[q].w };
#pragma unroll
        for (int c = 0; c < 4; c++)
            wcnt += __popc(__ballot_sync(0xFFFFFFFFu, u[c] >= T));
    }
    if (lane == 0) warpcnt[0][wid] = wcnt;
    __syncthreads();
    unsigned nc = 0, wbase = 0;
#pragma unroll
    for (int w = 0; w < 8; w++) {
        if (w < wid) wbase += warpcnt[0][w];
        nc += warpcnt[0][w];
    }
    if (nc > CANDN) nc = CANDN;
    {
        unsigned base = wbase;
        const unsigned ltmask = (1u << lane) - 1u;
#pragma unroll
        for (int q = 0; q < 6; q++) {
            const int c0 = q * 1024 + tid * 4;
            unsigned u[4] = { vb[q].x, vb[q].y, vb[q].z, vb[q].w };
#pragma unroll
            for (int c = 0; c < 4; c++) {
                const bool pred = (u[c] >= T);
                const unsigned m = __ballot_sync(0xFFFFFFFFu, pred);
                if (pred) {
                    unsigned slot = base + __popc(m & ltmask);
                    if (slot < CANDN) { cu[slot] = u[c]; ci[slot] = c0 + c; }
                }
                base += __popc(m);
            }
        }
    }
    __syncthreads();

    // ---- phase 3: exact rank (value desc, index asc) over candidates
    float* vrow = g_vals + row * KSEL;
    int*   irow = g_idx  + row * KSEL;
    for (unsigned j = tid; j < nc; j += 256) {
        const unsigned v = cu[j];
        const int id = ci[j];
        int r = 0;
        for (unsigned m = 0; m < nc; m++) {
            const unsigned w = cu[m];
            r += (w > v) || (w == v && ci[m] < id);
        }
        if (r < KSEL) { vrow[r] = __uint_as_float(v); irow[r] = id; }
        if (r == KSEL - 1) s_T64 = v;
        if (r == KSEL)     s_v65 = v;
    }
    __syncthreads();
    const unsigned T64 = s_T64;

    // ---- phase 4: write sparse, track non-candidate max
    float* srow = sparse + (size_t)row * FDIM;
    unsigned bmax = 0;
#pragma unroll
    for (int q = 0; q < 6; q++) {
        const int c0 = q * 1024 + tid * 4;
        unsigned u[4] = { vb[q].x, vb[q].y, vb[q].z, vb[q].w };
        float o[4];
#pragma unroll
        for (int c = 0; c < 4; c++) {
            o[c] = (u[c] > T64) ? __uint_as_float(u[c]) : 0.f;
            if (u[c] < T) bmax = max(bmax, u[c]);
        }
        *(float4*)&srow[c0] = *(const float4*)o;
    }
#pragma unroll
    for (int o2 = 16; o2; o2 >>= 1) bmax = max(bmax, __shfl_xor_sync(0xFFFFFFFFu, bmax, o2));
    if (lane == 0) warpmax[wid] = bmax;
    __syncthreads();

    if (tid < KSEL) srow[irow[tid]] = vrow[tid];

    if (tid == 0) {
        unsigned below;
        if (nc > KSEL) below = s_v65;
        else {
            below = 0;
#pragma unroll
            for (int w = 0; w < 8; w++) below = max(below, warpmax[w]);
        }
        g_T[row] = T64;
        const float gap = __uint_as_float(T64) - __uint_as_float(below);
        if (T64 != 0u && gap < GAP_TAU) {
            unsigned p = atomicAdd(&g_nflag, 1u);
            if (p < MAXFLAG) g_flagrows[p] = row;
        }
    }
}

// ---- exact repair of flagged rows -------------------------------------------------
__global__ void __launch_bounds__(256) repair_kernel(
    const float* __restrict__ x, const float* __restrict__ Wi,
    const float* __restrict__ bi, float* __restrict__ sparse)
{
    __shared__ float xs[DDIM];
    __shared__ int   cand[CAND_MAX];
    __shared__ float cex[CAND_MAX];
    __shared__ float red[256];
    __shared__ unsigned s_nc, s_nhi;

    unsigned nf = min(g_nflag, (unsigned)MAXFLAG);
    if (blockIdx.x >= nf) return;
    const int row = g_flagrows[blockIdx.x];
    const int tid = threadIdx.x;
    const float Tval = __uint_as_float(g_T[row]);
    const float* hrow = g_h + (size_t)row * FDIM;

    for (int i = tid; i < DDIM; i += 256) xs[i] = x[(size_t)row * DDIM + i];
    if (tid == 0) { s_nc = 0; s_nhi = 0; }
    __syncthreads();

    unsigned nhi_loc = 0;
    for (int f = tid; f < FDIM; f += 256) {
        float v = hrow[f];
        if (fabsf(v - Tval) <= GAP_TAU) {
            unsigned p = atomicAdd(&s_nc, 1u);
            if (p < CAND_MAX) cand[p] = f;
        } else if (v > Tval) nhi_loc++;
    }
    atomicAdd(&s_nhi, nhi_loc);
    __syncthreads();
    const unsigned nc = s_nc;
    if (nc > CAND_MAX) return;

    for (unsigned j = 0; j < nc; j++) {
        const int f = cand[j];
        float s = 0.f, c = 0.f;
        for (int d = tid; d < DDIM; d += 256) {
            float p = __fmaf_rn(xs[d], Wi[(size_t)d * FDIM + f], 0.f);
            float y = __fsub_rn(p, c);
            float t2 = __fadd_rn(s, y);
            c = __fsub_rn(__fsub_rn(t2, s), y);
            s = t2;
        }
        red[tid] = s;
        __syncthreads();
        for (int o = 128; o > 0; o >>= 1) {
            if (tid < o) red[tid] = __fadd_rn(red[tid], red[tid + o]);
            __syncthreads();
        }
        if (tid == 0) {
            float v = __fadd_rn(red[0], bi[f]);
            cex[j] = (v > 0.f) ? v : 0.f;
        }
        __syncthreads();
    }
    if (tid != 0) return;

    float* srow = sparse + (size_t)row * FDIM;
    float* vrow = g_vals + row * KSEL;
    int*   irow = g_idx  + row * KSEL;

    int k_rem = KSEL - (int)s_nhi;
    bool want[CAND_MAX], cur[CAND_MAX];
    for (unsigned j = 0; j < nc; j++) {
        want[j] = false;
        cur[j] = (srow[cand[j]] != 0.f);
    }
    for (int slot = 0; slot < k_rem; slot++) {
        int best = -1;
        for (unsigned j = 0; j < nc; j++) {
            if (want[j]) continue;
            if (best < 0 || cex[j] > cex[best] ||
                (cex[j] == cex[best] && cand[j] < cand[best])) best = (int)j;
        }
        if (best >= 0) want[best] = true;
    }
    int addq[CAND_MAX]; int na = 0;
    for (unsigned j = 0; j < nc; j++) if (want[j] && !cur[j]) addq[na++] = (int)j;
    int ai = 0;
    for (unsigned j = 0; j < nc && ai < na; j++) {
        if (cur[j] && !want[j]) {
            int rf = cand[j];
            int af = cand[addq[ai]]; ai++;
            float av = hrow[af];
            srow[rf] = 0.f;
            srow[af] = av;
            for (int q = 0; q < KSEL; q++)
                if (irow[q] == rf) { irow[q] = af; vrow[q] = av; break; }
        }
    }
}

// ---- classifier (fp32 gather — R10-proven) -------------------------------------------
__global__ void __launch_bounds__(256) cls_kernel(
    const float* __restrict__ Wc, const float* __restrict__ bc,
    float* __restrict__ logits)
{
    const int row = blockIdx.x;
    const int tid = threadIdx.x;
    __shared__ float sv[KSEL];
    __shared__ int   si[KSEL];
    if (tid < KSEL) {
        sv[tid] = g_vals[row * KSEL + tid];
        si[tid] = g_idx [row * KSEL + tid];
    }
    __syncthreads();
    if (tid >= 250) return;
    const int c = tid * 4;
    float4 acc = *(const float4*)&bc[c];
#pragma unroll 4
    for (int j = 0; j < KSEL; j++) {
        const float v = sv[j];
        const float4 w = *(const float4*)&Wc[(size_t)si[j] * CDIM + c];
        acc.x = fmaf(v, w.x, acc.x);
        acc.y = fmaf(v, w.y, acc.y);
        acc.z = fmaf(v, w.z, acc.z);
        acc.w = fmaf(v, w.w, acc.w);
    }
    *(float4*)&logits[(size_t)row * CDIM + c] = acc;
}

// ----------------------------------------------------------------------------------------
extern "C" void kernel_launch(void* const* d_in, const int* in_sizes, int n_in,
                              void* d_out, int out_size)
{
    const float* x  = (const float*)d_in[0];
    const float* Wi = (const float*)d_in[1];
    const float* bi = (const float*)d_in[2];
    const float* Wc = (const float*)d_in[3];
    const float* bc = (const float*)d_in[4];
    (void)in_sizes; (void)n_in; (void)out_size;

    float* sparse = (float*)d_out;
    float* logits = (float*)d_out + (size_t)BDIM * FDIM;

    static int smem_set = 0;
    if (!smem_set) {
        cudaFuncSetAttribute(mma_gemm, cudaFuncAttributeMaxDynamicSharedMemorySize, SMEMDYN);
        smem_set = 1;
    }

    split_fused<<<BT_BLOCKS + A_BLOCKS, 256>>>(x, Wi);
    mma_gemm<<<dim3(FDIM / 128, BDIM / 128), 256, SMEMDYN>>>(bi);
    topk_kernel<<<BDIM, 256>>>(sparse);
    repair_kernel<<<MAXFLAG, 256>>>(x, Wi, bi, sparse);
    cls_kernel<<<BDIM, 256>>>(Wc, bc, logits);
}

// round 15
// speedup vs baseline: 1.5089x; 1.0876x over previous
#include <cuda_runtime.h>
#include <cuda_fp16.h>
#include <cstdint>

#define BDIM 4096
#define DDIM 768
#define FDIM 6144
#define CDIM 1000
#define KSEL 64

// ---- mma-GEMM tiling (R10-proven): 128x128 CTA tile, 256 threads ---------------
#define KC2 32
#define NCH (DDIM / KC2)          // 24
#define ROWBYTES 80               // 32 fp16 (64B) + 16B pad: conflict-free ldmatrix
#define TILEB (128 * ROWBYTES)    // 10240 B
#define BUFB (4 * TILEB)          // Ah, Am, Bh, Bm = 40960
#define SMEMDYN (2 * BUFB)        // 81920 B

#define MAXFLAG 4096
#define CAND_MAX 64
#define GAP_TAU 2e-5f

// top-k candidate machinery
#define CANDN 256
#define BREAK_CNT 160

// fused split kernel partition
#define BT_BLOCKS ((FDIM / 32) * (DDIM / 32))   // 4608
#define A_BLOCKS 1024

// ---- scratch ------------------------------------------------------------------
__device__ float g_h[(size_t)BDIM * FDIM];
__device__ float g_vals[BDIM * KSEL];
__device__ int   g_idx [BDIM * KSEL];
__device__ unsigned g_T[BDIM];
__device__ unsigned g_nflag;
__device__ int   g_flagrows[MAXFLAG];
__device__ __half gAh[(size_t)BDIM * DDIM];
__device__ __half gAm[(size_t)BDIM * DDIM];
__device__ __half gBh[(size_t)FDIM * DDIM];   // W_inter^T limbs, [n][k]
__device__ __half gBm[(size_t)FDIM * DDIM];

// ---- helpers -------------------------------------------------------------------
__device__ __forceinline__ uint32_t smem_u32(const void* p) {
    uint32_t a;
    asm("{ .reg .u64 t; cvta.to.shared.u64 t, %1; cvt.u32.u64 %0, t; }" : "=r"(a) : "l"(p));
    return a;
}
__device__ __forceinline__ void cp_async16(uint32_t dst, const void* src) {
    asm volatile("cp.async.cg.shared.global [%0], [%1], 16;" :: "r"(dst), "l"(src));
}
__device__ __forceinline__ void ldsm4(uint32_t* r, uint32_t addr) {
    asm volatile("ldmatrix.sync.aligned.m8n8.x4.shared.b16 {%0,%1,%2,%3}, [%4];"
                 : "=r"(r[0]), "=r"(r[1]), "=r"(r[2]), "=r"(r[3]) : "r"(addr));
}
__device__ __forceinline__ void mma16816(float* d, const uint32_t* a, const uint32_t* b) {
    asm volatile("mma.sync.aligned.m16n8k16.row.col.f32.f16.f16.f32 "
                 "{%0,%1,%2,%3}, {%4,%5,%6,%7}, {%8,%9}, {%0,%1,%2,%3};"
                 : "+f"(d[0]), "+f"(d[1]), "+f"(d[2]), "+f"(d[3])
                 : "r"(a[0]), "r"(a[1]), "r"(a[2]), "r"(a[3]), "r"(b[0]), "r"(b[1]));
}

// ---- fused split kernel: exact 2-limb fp16 decomposition of A and W^T ------------
__global__ void __launch_bounds__(256) split_fused(const float* __restrict__ x,
                                                   const float* __restrict__ W)
{
    if (blockIdx.x == 0 && threadIdx.x == 0) g_nflag = 0;

    if (blockIdx.x < BT_BLOCKS) {
        // ---- W^T limbs (32x32 transpose tile)
        __shared__ float t[32][33];
        const int bid = blockIdx.x;
        const int n0 = (bid % (FDIM / 32)) * 32;
        const int k0 = (bid / (FDIM / 32)) * 32;
        const int tx = threadIdx.x & 31, ty = threadIdx.x >> 5;
#pragma unroll
        for (int i = 0; i < 32; i += 8)
            t[ty + i][tx] = W[(size_t)(k0 + ty + i) * FDIM + n0 + tx];
        __syncthreads();
#pragma unroll
        for (int i = 0; i < 32; i += 8) {
            float v = t[tx][ty + i];
            __half h = __float2half_rn(v);
            float r1 = v - __half2float(h);
            size_t o = (size_t)(n0 + ty + i) * DDIM + k0 + tx;
            gBh[o] = h; gBm[o] = __float2half_rn(r1);
        }
    } else {
        // ---- A limbs (contiguous chunks)
        const size_t n = (size_t)BDIM * DDIM;
        const unsigned aid = blockIdx.x - BT_BLOCKS;
        for (size_t i = (size_t)aid * 256 + threadIdx.x; i < n;
             i += (size_t)A_BLOCKS * 256) {
            float v = x[i];
            __half h = __float2half_rn(v);
            float r1 = v - __half2float(h);
            gAh[i] = h; gAm[i] = __float2half_rn(r1);
        }
    }
}

// ---- tensor-core GEMM: h = relu(x @ W + b), fp16x3 -------------------------------
__device__ __forceinline__ void load_tiles(uint32_t sbase, int buf, int ch,
                                           int bm, int bn, int tid)
{
    const uint32_t bb = sbase + buf * BUFB;
    const int k0 = ch * KC2;
    const __half* srcs[4] = { gAh, gAm, gBh, gBm };
#pragma unroll
    for (int t = 0; t < 4; t++) {
        const int rbase = (t < 2) ? bm : bn;
        const __half* sp = srcs[t] + (size_t)rbase * DDIM + k0;
        const uint32_t tb = bb + t * TILEB;
#pragma unroll
        for (int i = tid; i < 512; i += 256) {
            const int row = i >> 2, seg = i & 3;
            cp_async16(tb + row * ROWBYTES + seg * 16, sp + (size_t)row * DDIM + seg * 8);
        }
    }
    asm volatile("cp.async.commit_group;" ::: "memory");
}

__global__ void __launch_bounds__(256, 1) mma_gemm(const float* __restrict__ bias)
{
    extern __shared__ char dsm[];
    const uint32_t sbase = smem_u32(dsm);
    const int tid = threadIdx.x, wid = tid >> 5, lane = tid & 31;
    const int bm = blockIdx.y * 128, bn = blockIdx.x * 128;
    const int wm = (wid >> 2) * 64;
    const int wn = (wid & 3) * 32;

    float d[4][4][4];
#pragma unroll
    for (int i = 0; i < 4; i++)
#pragma unroll
        for (int j = 0; j < 4; j++)
#pragma unroll
            for (int q = 0; q < 4; q++) d[i][j][q] = 0.f;

    load_tiles(sbase, 0, 0, bm, bn, tid);
    load_tiles(sbase, 1, 1, bm, bn, tid);

    const uint32_t aoff = (uint32_t)(wm + (lane & 15)) * ROWBYTES + ((lane >> 4) * 8) * 2;
    const uint32_t boff = (uint32_t)(wn + ((lane >> 4) & 1) * 8 + (lane & 7)) * ROWBYTES
                        + (((lane >> 3) & 1) * 8) * 2;

#pragma unroll 1
    for (int ch = 0; ch < NCH; ch++) {
        const int buf = ch & 1;
        if (ch < NCH - 1) asm volatile("cp.async.wait_group 1;" ::: "memory");
        else              asm volatile("cp.async.wait_group 0;" ::: "memory");
        __syncthreads();

        const uint32_t bb = sbase + buf * BUFB;
#pragma unroll
        for (int kk = 0; kk < 2; kk++) {
            const uint32_t ko = kk * 32;
            uint32_t ah[4][4], am[4][4], bh[2][4], bmm[2][4];
#pragma unroll
            for (int ma = 0; ma < 4; ma++) {
                ldsm4(ah[ma], bb + 0 * TILEB + aoff + ma * 16 * ROWBYTES + ko);
                ldsm4(am[ma], bb + 1 * TILEB + aoff + ma * 16 * ROWBYTES + ko);
            }
#pragma unroll
            for (int pr = 0; pr < 2; pr++) {
                ldsm4(bh[pr],  bb + 2 * TILEB + boff + pr * 16 * ROWBYTES + ko);
                ldsm4(bmm[pr], bb + 3 * TILEB + boff + pr * 16 * ROWBYTES + ko);
            }
#pragma unroll
            for (int ma = 0; ma < 4; ma++)
#pragma unroll
                for (int na = 0; na < 4; na++) {
                    const uint32_t* bhf = &bh[na >> 1][(na & 1) * 2];
                    const uint32_t* bmf = &bmm[na >> 1][(na & 1) * 2];
                    mma16816(d[ma][na], ah[ma], bhf);   // h*h
                    mma16816(d[ma][na], ah[ma], bmf);   // h*m
                    mma16816(d[ma][na], am[ma], bhf);   // m*h
                }
        }
        __syncthreads();
        if (ch + 2 < NCH) load_tiles(sbase, buf, ch + 2, bm, bn, tid);
    }

#pragma unroll
    for (int na = 0; na < 4; na++) {
        const int n0g = bn + wn + na * 8 + (lane & 3) * 2;
        const float b0 = bias[n0g], b1 = bias[n0g + 1];
#pragma unroll
        for (int ma = 0; ma < 4; ma++) {
            const int m0g = bm + wm + ma * 16 + (lane >> 2);
            float v0 = __fadd_rn(d[ma][na][0], b0);
            float v1 = __fadd_rn(d[ma][na][1], b1);
            float v2 = __fadd_rn(d[ma][na][2], b0);
            float v3 = __fadd_rn(d[ma][na][3], b1);
            float2 o0 = { (v0 > 0.f) ? v0 : 0.f, (v1 > 0.f) ? v1 : 0.f };
            float2 o1 = { (v2 > 0.f) ? v2 : 0.f, (v3 > 0.f) ? v3 : 0.f };
            *(float2*)&g_h[(size_t)m0g * FDIM + n0g]       = o0;
            *(float2*)&g_h[(size_t)(m0g + 8) * FDIM + n0g] = o1;
        }
    }
}

// ---- top-64: truncated bitwise search + exact candidate ranking -------------------
__global__ void __launch_bounds__(256) topk_kernel(float* __restrict__ sparse)
{
    const int row = blockIdx.x;
    const int tid = threadIdx.x;
    const int lane = tid & 31, wid = tid >> 5;

    __shared__ unsigned warpcnt[2][8];
    __shared__ unsigned warpmax[8];
    __shared__ unsigned cu[CANDN];
    __shared__ int      ci[CANDN];
    __shared__ unsigned s_T64, s_v65;

    const float* hrow = g_h + (size_t)row * FDIM;
    uint4 vb[6];
#pragma unroll
    for (int q = 0; q < 6; q++)
        vb[q] = ((const uint4*)hrow)[q * 256 + tid];

    if (tid == 0) { s_T64 = 0u; s_v65 = 0u; }

    // ---- phase 1: truncated greedy bit search
    unsigned T = 0, curcnt = FDIM;
#pragma unroll 1
    for (int b = 30; b >= 0; --b) {
        const unsigned cand = T | (1u << b);
        unsigned lc = 0;
#pragma unroll
        for (int q = 0; q < 6; q++) {
            lc += (vb[q].x >= cand) + (vb[q].y >= cand)
                + (vb[q].z >= cand) + (vb[q].w >= cand);
        }
        lc = __reduce_add_sync(0xFFFFFFFFu, lc);
        const int pb = b & 1;
        if (lane == 0) warpcnt[pb][wid] = lc;
        __syncthreads();
        unsigned cnt = 0;
#pragma unroll
        for (int w = 0; w < 8; w++) cnt += warpcnt[pb][w];
        if (cnt >= KSEL) { T = cand; curcnt = cnt; }
        if (curcnt <= BREAK_CNT) break;
    }
    __syncthreads();

    // ---- phase 2: atomic-free ballot compaction of candidates {u >= T}
    unsigned wcnt = 0;
#pragma unroll
    for (int q = 0; q < 6; q++) {
        unsigned u[4] = { vb[q].x, vb[q].y, vb[q].z, vb[q].w };
#pragma unroll
        for (int c = 0; c < 4; c++)
            wcnt += __popc(__ballot_sync(0xFFFFFFFFu, u[c] >= T));
    }
    if (lane == 0) warpcnt[0][wid] = wcnt;
    __syncthreads();
    unsigned nc = 0, wbase = 0;
#pragma unroll
    for (int w = 0; w < 8; w++) {
        if (w < wid) wbase += warpcnt[0][w];
        nc += warpcnt[0][w];
    }
    if (nc > CANDN) nc = CANDN;
    {
        unsigned base = wbase;
        const unsigned ltmask = (1u << lane) - 1u;
#pragma unroll
        for (int q = 0; q < 6; q++) {
            const int c0 = q * 1024 + tid * 4;
            unsigned u[4] = { vb[q].x, vb[q].y, vb[q].z, vb[q].w };
#pragma unroll
            for (int c = 0; c < 4; c++) {
                const bool pred = (u[c] >= T);
                const unsigned m = __ballot_sync(0xFFFFFFFFu, pred);
                if (pred) {
                    unsigned slot = base + __popc(m & ltmask);
                    if (slot < CANDN) { cu[slot] = u[c]; ci[slot] = c0 + c; }
                }
                base += __popc(m);
            }
        }
    }
    __syncthreads();

    // ---- phase 3: exact rank (value desc, index asc) over candidates
    float* vrow = g_vals + row * KSEL;
    int*   irow = g_idx  + row * KSEL;
    for (unsigned j = tid; j < nc; j += 256) {
        const unsigned v = cu[j];
        const int id = ci[j];
        int r = 0;
        for (unsigned m = 0; m < nc; m++) {
            const unsigned w = cu[m];
            r += (w > v) || (w == v && ci[m] < id);
        }
        if (r < KSEL) { vrow[r] = __uint_as_float(v); irow[r] = id; }
        if (r == KSEL - 1) s_T64 = v;
        if (r == KSEL)     s_v65 = v;
    }
    __syncthreads();
    const unsigned T64 = s_T64;

    // ---- phase 4: write sparse, track non-candidate max
    float* srow = sparse + (size_t)row * FDIM;
    unsigned bmax = 0;
#pragma unroll
    for (int q = 0; q < 6; q++) {
        const int c0 = q * 1024 + tid * 4;
        unsigned u[4] = { vb[q].x, vb[q].y, vb[q].z, vb[q].w };
        float o[4];
#pragma unroll
        for (int c = 0; c < 4; c++) {
            o[c] = (u[c] > T64) ? __uint_as_float(u[c]) : 0.f;
            if (u[c] < T) bmax = max(bmax, u[c]);
        }
        *(float4*)&srow[c0] = *(const float4*)o;
    }
#pragma unroll
    for (int o2 = 16; o2; o2 >>= 1) bmax = max(bmax, __shfl_xor_sync(0xFFFFFFFFu, bmax, o2));
    if (lane == 0) warpmax[wid] = bmax;
    __syncthreads();

    if (tid < KSEL) srow[irow[tid]] = vrow[tid];

    if (tid == 0) {
        unsigned below;
        if (nc > KSEL) below = s_v65;
        else {
            below = 0;
#pragma unroll
            for (int w = 0; w < 8; w++) below = max(below, warpmax[w]);
        }
        g_T[row] = T64;
        const float gap = __uint_as_float(T64) - __uint_as_float(below);
        if (T64 != 0u && gap < GAP_TAU) {
            unsigned p = atomicAdd(&g_nflag, 1u);
            if (p < MAXFLAG) g_flagrows[p] = row;
        }
    }
}

// ---- exact repair of flagged rows -------------------------------------------------
__global__ void __launch_bounds__(256) repair_kernel(
    const float* __restrict__ x, const float* __restrict__ Wi,
    const float* __restrict__ bi, float* __restrict__ sparse)
{
    __shared__ float xs[DDIM];
    __shared__ int   cand[CAND_MAX];
    __shared__ float cex[CAND_MAX];
    __shared__ float red[256];
    __shared__ unsigned s_nc, s_nhi;

    unsigned nf = min(g_nflag, (unsigned)MAXFLAG);
    if (blockIdx.x >= nf) return;
    const int row = g_flagrows[blockIdx.x];
    const int tid = threadIdx.x;
    const float Tval = __uint_as_float(g_T[row]);
    const float* hrow = g_h + (size_t)row * FDIM;

    for (int i = tid; i < DDIM; i += 256) xs[i] = x[(size_t)row * DDIM + i];
    if (tid == 0) { s_nc = 0; s_nhi = 0; }
    __syncthreads();

    unsigned nhi_loc = 0;
    for (int f = tid; f < FDIM; f += 256) {
        float v = hrow[f];
        if (fabsf(v - Tval) <= GAP_TAU) {
            unsigned p = atomicAdd(&s_nc, 1u);
            if (p < CAND_MAX) cand[p] = f;
        } else if (v > Tval) nhi_loc++;
    }
    atomicAdd(&s_nhi, nhi_loc);
    __syncthreads();
    const unsigned nc = s_nc;
    if (nc > CAND_MAX) return;

    for (unsigned j = 0; j < nc; j++) {
        const int f = cand[j];
        float s = 0.f, c = 0.f;
        for (int d = tid; d < DDIM; d += 256) {
            float p = __fmaf_rn(xs[d], Wi[(size_t)d * FDIM + f], 0.f);
            float y = __fsub_rn(p, c);
            float t2 = __fadd_rn(s, y);
            c = __fsub_rn(__fsub_rn(t2, s), y);
            s = t2;
        }
        red[tid] = s;
        __syncthreads();
        for (int o = 128; o > 0; o >>= 1) {
            if (tid < o) red[tid] = __fadd_rn(red[tid], red[tid + o]);
            __syncthreads();
        }
        if (tid == 0) {
            float v = __fadd_rn(red[0], bi[f]);
            cex[j] = (v > 0.f) ? v : 0.f;
        }
        __syncthreads();
    }
    if (tid != 0) return;

    float* srow = sparse + (size_t)row * FDIM;
    float* vrow = g_vals + row * KSEL;
    int*   irow = g_idx  + row * KSEL;

    int k_rem = KSEL - (int)s_nhi;
    bool want[CAND_MAX], cur[CAND_MAX];
    for (unsigned j = 0; j < nc; j++) {
        want[j] = false;
        cur[j] = (srow[cand[j]] != 0.f);
    }
    for (int slot = 0; slot < k_rem; slot++) {
        int best = -1;
        for (unsigned j = 0; j < nc; j++) {
            if (want[j]) continue;
            if (best < 0 || cex[j] > cex[best] ||
                (cex[j] == cex[best] && cand[j] < cand[best])) best = (int)j;
        }
        if (best >= 0) want[best] = true;
    }
    int addq[CAND_MAX]; int na = 0;
    for (unsigned j = 0; j < nc; j++) if (want[j] && !cur[j]) addq[na++] = (int)j;
    int ai = 0;
    for (unsigned j = 0; j < nc && ai < na; j++) {
        if (cur[j] && !want[j]) {
            int rf = cand[j];
            int af = cand[addq[ai]]; ai++;
            float av = hrow[af];
            srow[rf] = 0.f;
            srow[af] = av;
            for (int q = 0; q < KSEL; q++)
                if (irow[q] == rf) { irow[q] = af; vrow[q] = av; break; }
        }
    }
}

// ---- classifier (fp32 gather — R10-proven) -------------------------------------------
__global__ void __launch_bounds__(256) cls_kernel(
    const float* __restrict__ Wc, const float* __restrict__ bc,
    float* __restrict__ logits)
{
    const int row = blockIdx.x;
    const int tid = threadIdx.x;
    __shared__ float sv[KSEL];
    __shared__ int   si[KSEL];
    if (tid < KSEL) {
        sv[tid] = g_vals[row * KSEL + tid];
        si[tid] = g_idx [row * KSEL + tid];
    }
    __syncthreads();
    if (tid >= 250) return;
    const int c = tid * 4;
    float4 acc = *(const float4*)&bc[c];
#pragma unroll 4
    for (int j = 0; j < KSEL; j++) {
        const float v = sv[j];
        const float4 w = *(const float4*)&Wc[(size_t)si[j] * CDIM + c];
        acc.x = fmaf(v, w.x, acc.x);
        acc.y = fmaf(v, w.y, acc.y);
        acc.z = fmaf(v, w.z, acc.z);
        acc.w = fmaf(v, w.w, acc.w);
    }
    *(float4*)&logits[(size_t)row * CDIM + c] = acc;
}

// ----------------------------------------------------------------------------------------
extern "C" void kernel_launch(void* const* d_in, const int* in_sizes, int n_in,
                              void* d_out, int out_size)
{
    const float* x  = (const float*)d_in[0];
    const float* Wi = (const float*)d_in[1];
    const float* bi = (const float*)d_in[2];
    const float* Wc = (const float*)d_in[3];
    const float* bc = (const float*)d_in[4];
    (void)in_sizes; (void)n_in; (void)out_size;

    float* sparse = (float*)d_out;
    float* logits = (float*)d_out + (size_t)BDIM * FDIM;

    static int smem_set = 0;
    if (!smem_set) {
        cudaFuncSetAttribute(mma_gemm, cudaFuncAttributeMaxDynamicSharedMemorySize, SMEMDYN);
        smem_set = 1;
    }

    split_fused<<<BT_BLOCKS + A_BLOCKS, 256>>>(x, Wi);
    mma_gemm<<<dim3(FDIM / 128, BDIM / 128), 256, SMEMDYN>>>(bi);
    topk_kernel<<<BDIM, 256>>>(sparse);
    repair_kernel<<<MAXFLAG, 256>>>(x, Wi, bi, sparse);
    cls_kernel<<<BDIM, 256>>>(Wc, bc, logits);
}

// round 16
// speedup vs baseline: 1.6624x; 1.1017x over previous
#include <cuda_runtime.h>
#include <cuda_fp16.h>
#include <cstdint>

#define BDIM 4096
#define DDIM 768
#define FDIM 6144
#define CDIM 1000
#define KSEL 64

// ---- mma-GEMM tiling: 128x128 CTA tile, 256 threads, SINGLE fp16 pass ----------
#define KC2 32
#define NCH (DDIM / KC2)          // 24
#define ROWBYTES 80               // 32 fp16 (64B) + 16B pad: conflict-free ldmatrix
#define TILEB (128 * ROWBYTES)    // 10240 B
#define BUFB (2 * TILEB)          // Ah, Bh = 20480
#define SMEMDYN (2 * BUFB)        // 40960 B

#define MAXFLAG 4096
#define CAND_MAX 64
#define GAP_TAU 5e-3f             // covers 2*err_max of single-pass fp16 (err_max~2e-3)

// top-k candidate machinery
#define CANDN 256
#define BREAK_CNT 160

// fused split kernel partition
#define BT_BLOCKS ((FDIM / 32) * (DDIM / 32))   // 4608
#define A_BLOCKS 1024

// ---- scratch ------------------------------------------------------------------
__device__ float g_h[(size_t)BDIM * FDIM];
__device__ float g_vals[BDIM * KSEL];
__device__ int   g_idx [BDIM * KSEL];
__device__ unsigned g_T[BDIM];
__device__ unsigned g_nflag;
__device__ int   g_flagrows[MAXFLAG];
__device__ __half gAh[(size_t)BDIM * DDIM];
__device__ __half gBh[(size_t)FDIM * DDIM];   // W_inter^T fp16, [n][k]

// ---- helpers -------------------------------------------------------------------
__device__ __forceinline__ uint32_t smem_u32(const void* p) {
    uint32_t a;
    asm("{ .reg .u64 t; cvta.to.shared.u64 t, %1; cvt.u32.u64 %0, t; }" : "=r"(a) : "l"(p));
    return a;
}
__device__ __forceinline__ void cp_async16(uint32_t dst, const void* src) {
    asm volatile("cp.async.cg.shared.global [%0], [%1], 16;" :: "r"(dst), "l"(src));
}
__device__ __forceinline__ void ldsm4(uint32_t* r, uint32_t addr) {
    asm volatile("ldmatrix.sync.aligned.m8n8.x4.shared.b16 {%0,%1,%2,%3}, [%4];"
                 : "=r"(r[0]), "=r"(r[1]), "=r"(r[2]), "=r"(r[3]) : "r"(addr));
}
__device__ __forceinline__ void mma16816(float* d, const uint32_t* a, const uint32_t* b) {
    asm volatile("mma.sync.aligned.m16n8k16.row.col.f32.f16.f16.f32 "
                 "{%0,%1,%2,%3}, {%4,%5,%6,%7}, {%8,%9}, {%0,%1,%2,%3};"
                 : "+f"(d[0]), "+f"(d[1]), "+f"(d[2]), "+f"(d[3])
                 : "r"(a[0]), "r"(a[1]), "r"(a[2]), "r"(a[3]), "r"(b[0]), "r"(b[1]));
}

// ---- fused split kernel: fp16 rounding of A and W^T --------------------------------
__global__ void __launch_bounds__(256) split_fused(const float* __restrict__ x,
                                                   const float* __restrict__ W)
{
    if (blockIdx.x == 0 && threadIdx.x == 0) g_nflag = 0;

    if (blockIdx.x < BT_BLOCKS) {
        // ---- W^T fp16 (32x32 transpose tile)
        __shared__ float t[32][33];
        const int bid = blockIdx.x;
        const int n0 = (bid % (FDIM / 32)) * 32;
        const int k0 = (bid / (FDIM / 32)) * 32;
        const int tx = threadIdx.x & 31, ty = threadIdx.x >> 5;
#pragma unroll
        for (int i = 0; i < 32; i += 8)
            t[ty + i][tx] = W[(size_t)(k0 + ty + i) * FDIM + n0 + tx];
        __syncthreads();
#pragma unroll
        for (int i = 0; i < 32; i += 8) {
            float v = t[tx][ty + i];
            gBh[(size_t)(n0 + ty + i) * DDIM + k0 + tx] = __float2half_rn(v);
        }
    } else {
        // ---- A fp16 (contiguous chunks)
        const size_t n = (size_t)BDIM * DDIM;
        const unsigned aid = blockIdx.x - BT_BLOCKS;
        for (size_t i = (size_t)aid * 256 + threadIdx.x; i < n;
             i += (size_t)A_BLOCKS * 256) {
            gAh[i] = __float2half_rn(x[i]);
        }
    }
}

// ---- tensor-core GEMM: h ~= relu(x @ W + b), single fp16 pass ----------------------
__device__ __forceinline__ void load_tiles(uint32_t sbase, int buf, int ch,
                                           int bm, int bn, int tid)
{
    const uint32_t bb = sbase + buf * BUFB;
    const int k0 = ch * KC2;
    const __half* srcs[2] = { gAh, gBh };
#pragma unroll
    for (int t = 0; t < 2; t++) {
        const int rbase = (t == 0) ? bm : bn;
        const __half* sp = srcs[t] + (size_t)rbase * DDIM + k0;
        const uint32_t tb = bb + t * TILEB;
#pragma unroll
        for (int i = tid; i < 512; i += 256) {
            const int row = i >> 2, seg = i & 3;
            cp_async16(tb + row * ROWBYTES + seg * 16, sp + (size_t)row * DDIM + seg * 8);
        }
    }
    asm volatile("cp.async.commit_group;" ::: "memory");
}

__global__ void __launch_bounds__(256, 1) mma_gemm(const float* __restrict__ bias)
{
    extern __shared__ char dsm[];
    const uint32_t sbase = smem_u32(dsm);
    const int tid = threadIdx.x, wid = tid >> 5, lane = tid & 31;
    const int bm = blockIdx.y * 128, bn = blockIdx.x * 128;
    const int wm = (wid >> 2) * 64;
    const int wn = (wid & 3) * 32;

    float d[4][4][4];
#pragma unroll
    for (int i = 0; i < 4; i++)
#pragma unroll
        for (int j = 0; j < 4; j++)
#pragma unroll
            for (int q = 0; q < 4; q++) d[i][j][q] = 0.f;

    load_tiles(sbase, 0, 0, bm, bn, tid);
    load_tiles(sbase, 1, 1, bm, bn, tid);

    const uint32_t aoff = (uint32_t)(wm + (lane & 15)) * ROWBYTES + ((lane >> 4) * 8) * 2;
    const uint32_t boff = (uint32_t)(wn + ((lane >> 4) & 1) * 8 + (lane & 7)) * ROWBYTES
                        + (((lane >> 3) & 1) * 8) * 2;

#pragma unroll 1
    for (int ch = 0; ch < NCH; ch++) {
        const int buf = ch & 1;
        if (ch < NCH - 1) asm volatile("cp.async.wait_group 1;" ::: "memory");
        else              asm volatile("cp.async.wait_group 0;" ::: "memory");
        __syncthreads();

        const uint32_t bb = sbase + buf * BUFB;
#pragma unroll
        for (int kk = 0; kk < 2; kk++) {
            const uint32_t ko = kk * 32;
            uint32_t ah[4][4], bh[2][4];
#pragma unroll
            for (int ma = 0; ma < 4; ma++)
                ldsm4(ah[ma], bb + aoff + ma * 16 * ROWBYTES + ko);
#pragma unroll
            for (int pr = 0; pr < 2; pr++)
                ldsm4(bh[pr], bb + TILEB + boff + pr * 16 * ROWBYTES + ko);
#pragma unroll
            for (int ma = 0; ma < 4; ma++)
#pragma unroll
                for (int na = 0; na < 4; na++)
                    mma16816(d[ma][na], ah[ma], &bh[na >> 1][(na & 1) * 2]);
        }
        __syncthreads();
        if (ch + 2 < NCH) load_tiles(sbase, buf, ch + 2, bm, bn, tid);
    }

#pragma unroll
    for (int na = 0; na < 4; na++) {
        const int n0g = bn + wn + na * 8 + (lane & 3) * 2;
        const float b0 = bias[n0g], b1 = bias[n0g + 1];
#pragma unroll
        for (int ma = 0; ma < 4; ma++) {
            const int m0g = bm + wm + ma * 16 + (lane >> 2);
            float v0 = __fadd_rn(d[ma][na][0], b0);
            float v1 = __fadd_rn(d[ma][na][1], b1);
            float v2 = __fadd_rn(d[ma][na][2], b0);
            float v3 = __fadd_rn(d[ma][na][3], b1);
            float2 o0 = { (v0 > 0.f) ? v0 : 0.f, (v1 > 0.f) ? v1 : 0.f };
            float2 o1 = { (v2 > 0.f) ? v2 : 0.f, (v3 > 0.f) ? v3 : 0.f };
            *(float2*)&g_h[(size_t)m0g * FDIM + n0g]       = o0;
            *(float2*)&g_h[(size_t)(m0g + 8) * FDIM + n0g] = o1;
        }
    }
}

// ---- top-64: truncated bitwise search + exact candidate ranking -------------------
__global__ void __launch_bounds__(256) topk_kernel(float* __restrict__ sparse)
{
    const int row = blockIdx.x;
    const int tid = threadIdx.x;
    const int lane = tid & 31, wid = tid >> 5;

    __shared__ unsigned warpcnt[2][8];
    __shared__ unsigned warpmax[8];
    __shared__ unsigned cu[CANDN];
    __shared__ int      ci[CANDN];
    __shared__ unsigned s_T64, s_v65;

    const float* hrow = g_h + (size_t)row * FDIM;
    uint4 vb[6];
#pragma unroll
    for (int q = 0; q < 6; q++)
        vb[q] = ((const uint4*)hrow)[q * 256 + tid];

    if (tid == 0) { s_T64 = 0u; s_v65 = 0u; }

    // ---- phase 1: truncated greedy bit search
    unsigned T = 0, curcnt = FDIM;
#pragma unroll 1
    for (int b = 30; b >= 0; --b) {
        const unsigned cand = T | (1u << b);
        unsigned lc = 0;
#pragma unroll
        for (int q = 0; q < 6; q++) {
            lc += (vb[q].x >= cand) + (vb[q].y >= cand)
                + (vb[q].z >= cand) + (vb[q].w >= cand);
        }
        lc = __reduce_add_sync(0xFFFFFFFFu, lc);
        const int pb = b & 1;
        if (lane == 0) warpcnt[pb][wid] = lc;
        __syncthreads();
        unsigned cnt = 0;
#pragma unroll
        for (int w = 0; w < 8; w++) cnt += warpcnt[pb][w];
        if (cnt >= KSEL) { T = cand; curcnt = cnt; }
        if (curcnt <= BREAK_CNT) break;
    }
    __syncthreads();

    // ---- phase 2: atomic-free ballot compaction of candidates {u >= T}
    unsigned wcnt = 0;
#pragma unroll
    for (int q = 0; q < 6; q++) {
        unsigned u[4] = { vb[q].x, vb[q].y, vb[q].z, vb[q].w };
#pragma unroll
        for (int c = 0; c < 4; c++)
            wcnt += __popc(__ballot_sync(0xFFFFFFFFu, u[c] >= T));
    }
    if (lane == 0) warpcnt[0][wid] = wcnt;
    __syncthreads();
    unsigned nc = 0, wbase = 0;
#pragma unroll
    for (int w = 0; w < 8; w++) {
        if (w < wid) wbase += warpcnt[0][w];
        nc += warpcnt[0][w];
    }
    if (nc > CANDN) nc = CANDN;
    {
        unsigned base = wbase;
        const unsigned ltmask = (1u << lane) - 1u;
#pragma unroll
        for (int q = 0; q < 6; q++) {
            const int c0 = q * 1024 + tid * 4;
            unsigned u[4] = { vb[q].x, vb[q].y, vb[q].z, vb[q].w };
#pragma unroll
            for (int c = 0; c < 4; c++) {
                const bool pred = (u[c] >= T);
                const unsigned m = __ballot_sync(0xFFFFFFFFu, pred);
                if (pred) {
                    unsigned slot = base + __popc(m & ltmask);
                    if (slot < CANDN) { cu[slot] = u[c]; ci[slot] = c0 + c; }
                }
                base += __popc(m);
            }
        }
    }
    __syncthreads();

    // ---- phase 3: exact rank (value desc, index asc) over candidates
    float* vrow = g_vals + row * KSEL;
    int*   irow = g_idx  + row * KSEL;
    for (unsigned j = tid; j < nc; j += 256) {
        const unsigned v = cu[j];
        const int id = ci[j];
        int r = 0;
        for (unsigned m = 0; m < nc; m++) {
            const unsigned w = cu[m];
            r += (w > v) || (w == v && ci[m] < id);
        }
        if (r < KSEL) { vrow[r] = __uint_as_float(v); irow[r] = id; }
        if (r == KSEL - 1) s_T64 = v;
        if (r == KSEL)     s_v65 = v;
    }
    __syncthreads();
    const unsigned T64 = s_T64;

    // ---- phase 4: write sparse, track non-candidate max
    float* srow = sparse + (size_t)row * FDIM;
    unsigned bmax = 0;
#pragma unroll
    for (int q = 0; q < 6; q++) {
        const int c0 = q * 1024 + tid * 4;
        unsigned u[4] = { vb[q].x, vb[q].y, vb[q].z, vb[q].w };
        float o[4];
#pragma unroll
        for (int c = 0; c < 4; c++) {
            o[c] = (u[c] > T64) ? __uint_as_float(u[c]) : 0.f;
            if (u[c] < T) bmax = max(bmax, u[c]);
        }
        *(float4*)&srow[c0] = *(const float4*)o;
    }
#pragma unroll
    for (int o2 = 16; o2; o2 >>= 1) bmax = max(bmax, __shfl_xor_sync(0xFFFFFFFFu, bmax, o2));
    if (lane == 0) warpmax[wid] = bmax;
    __syncthreads();

    if (tid < KSEL) srow[irow[tid]] = vrow[tid];

    if (tid == 0) {
        unsigned below;
        if (nc > KSEL) below = s_v65;
        else {
            below = 0;
#pragma unroll
            for (int w = 0; w < 8; w++) below = max(below, warpmax[w]);
        }
        g_T[row] = T64;
        const float gap = __uint_as_float(T64) - __uint_as_float(below);
        if (T64 != 0u && gap < GAP_TAU) {
            unsigned p = atomicAdd(&g_nflag, 1u);
            if (p < MAXFLAG) g_flagrows[p] = row;
        }
    }
}

// ---- exact repair of flagged rows (fp32 Kahan, certifies selection) ----------------
__global__ void __launch_bounds__(256) repair_kernel(
    const float* __restrict__ x, const float* __restrict__ Wi,
    const float* __restrict__ bi, float* __restrict__ sparse)
{
    __shared__ float xs[DDIM];
    __shared__ int   cand[CAND_MAX];
    __shared__ float cex[CAND_MAX];
    __shared__ float red[256];
    __shared__ unsigned s_nc, s_nhi;

    unsigned nf = min(g_nflag, (unsigned)MAXFLAG);
    if (blockIdx.x >= nf) return;
    const int row = g_flagrows[blockIdx.x];
    const int tid = threadIdx.x;
    const float Tval = __uint_as_float(g_T[row]);
    const float* hrow = g_h + (size_t)row * FDIM;

    for (int i = tid; i < DDIM; i += 256) xs[i] = x[(size_t)row * DDIM + i];
    if (tid == 0) { s_nc = 0; s_nhi = 0; }
    __syncthreads();

    unsigned nhi_loc = 0;
    for (int f = tid; f < FDIM; f += 256) {
        float v = hrow[f];
        if (fabsf(v - Tval) <= GAP_TAU) {
            unsigned p = atomicAdd(&s_nc, 1u);
            if (p < CAND_MAX) cand[p] = f;
        } else if (v > Tval) nhi_loc++;
    }
    atomicAdd(&s_nhi, nhi_loc);
    __syncthreads();
    const unsigned nc = s_nc;
    if (nc > CAND_MAX) return;

    for (unsigned j = 0; j < nc; j++) {
        const int f = cand[j];
        float s = 0.f, c = 0.f;
        for (int d = tid; d < DDIM; d += 256) {
            float p = __fmaf_rn(xs[d], Wi[(size_t)d * FDIM + f], 0.f);
            float y = __fsub_rn(p, c);
            float t2 = __fadd_rn(s, y);
            c = __fsub_rn(__fsub_rn(t2, s), y);
            s = t2;
        }
        red[tid] = s;
        __syncthreads();
        for (int o = 128; o > 0; o >>= 1) {
            if (tid < o) red[tid] = __fadd_rn(red[tid], red[tid + o]);
            __syncthreads();
        }
        if (tid == 0) {
            float v = __fadd_rn(red[0], bi[f]);
            cex[j] = (v > 0.f) ? v : 0.f;
        }
        __syncthreads();
    }
    if (tid != 0) return;

    float* srow = sparse + (size_t)row * FDIM;
    float* vrow = g_vals + row * KSEL;
    int*   irow = g_idx  + row * KSEL;

    int k_rem = KSEL - (int)s_nhi;
    bool want[CAND_MAX], cur[CAND_MAX];
    for (unsigned j = 0; j < nc; j++) {
        want[j] = false;
        cur[j] = (srow[cand[j]] != 0.f);
    }
    for (int slot = 0; slot < k_rem; slot++) {
        int best = -1;
        for (unsigned j = 0; j < nc; j++) {
            if (want[j]) continue;
            if (best < 0 || cex[j] > cex[best] ||
                (cex[j] == cex[best] && cand[j] < cand[best])) best = (int)j;
        }
        if (best >= 0) want[best] = true;
    }
    int addq[CAND_MAX]; int na = 0;
    for (unsigned j = 0; j < nc; j++) if (want[j] && !cur[j]) addq[na++] = (int)j;
    int ai = 0;
    for (unsigned j = 0; j < nc && ai < na; j++) {
        if (cur[j] && !want[j]) {
            int rf = cand[j];
            int af = cand[addq[ai]]; ai++;
            float av = hrow[af];
            srow[rf] = 0.f;
            srow[af] = av;
            for (int q = 0; q < KSEL; q++)
                if (irow[q] == rf) { irow[q] = af; vrow[q] = av; break; }
        }
    }
}

// ---- classifier (fp32 gather — proven) -------------------------------------------
__global__ void __launch_bounds__(256) cls_kernel(
    const float* __restrict__ Wc, const float* __restrict__ bc,
    float* __restrict__ logits)
{
    const int row = blockIdx.x;
    const int tid = threadIdx.x;
    __shared__ float sv[KSEL];
    __shared__ int   si[KSEL];
    if (tid < KSEL) {
        sv[tid] = g_vals[row * KSEL + tid];
        si[tid] = g_idx [row * KSEL + tid];
    }
    __syncthreads();
    if (tid >= 250) return;
    const int c = tid * 4;
    float4 acc = *(const float4*)&bc[c];
#pragma unroll 4
    for (int j = 0; j < KSEL; j++) {
        const float v = sv[j];
        const float4 w = *(const float4*)&Wc[(size_t)si[j] * CDIM + c];
        acc.x = fmaf(v, w.x, acc.x);
        acc.y = fmaf(v, w.y, acc.y);
        acc.z = fmaf(v, w.z, acc.z);
        acc.w = fmaf(v, w.w, acc.w);
    }
    *(float4*)&logits[(size_t)row * CDIM + c] = acc;
}

// ----------------------------------------------------------------------------------------
extern "C" void kernel_launch(void* const* d_in, const int* in_sizes, int n_in,
                              void* d_out, int out_size)
{
    const float* x  = (const float*)d_in[0];
    const float* Wi = (const float*)d_in[1];
    const float* bi = (const float*)d_in[2];
    const float* Wc = (const float*)d_in[3];
    const float* bc = (const float*)d_in[4];
    (void)in_sizes; (void)n_in; (void)out_size;

    float* sparse = (float*)d_out;
    float* logits = (float*)d_out + (size_t)BDIM * FDIM;

    static int smem_set = 0;
    if (!smem_set) {
        cudaFuncSetAttribute(mma_gemm, cudaFuncAttributeMaxDynamicSharedMemorySize, SMEMDYN);
        smem_set = 1;
    }

    split_fused<<<BT_BLOCKS + A_BLOCKS, 256>>>(x, Wi);
    mma_gemm<<<dim3(FDIM / 128, BDIM / 128), 256, SMEMDYN>>>(bi);
    topk_kernel<<<BDIM, 256>>>(sparse);
    repair_kernel<<<MAXFLAG, 256>>>(x, Wi, bi, sparse);
    cls_kernel<<<BDIM, 256>>>(Wc, bc, logits);
}

// round 17
// speedup vs baseline: 1.7680x; 1.0635x over previous
#include <cuda_runtime.h>
#include <cuda_fp16.h>
#include <cstdint>

#define BDIM 4096
#define DDIM 768
#define FDIM 6144
#define CDIM 1000
#define KSEL 64

// ---- mma-GEMM tiling: 128x128 CTA tile, 256 threads, SINGLE fp16 pass ----------
#define KC2 32
#define NCH (DDIM / KC2)          // 24
#define ROWBYTES 80               // 32 fp16 (64B) + 16B pad: conflict-free ldmatrix
#define TILEB (128 * ROWBYTES)    // 10240 B
#define BUFB (2 * TILEB)          // Ah, Bh = 20480
#define SMEMDYN (2 * BUFB)        // 40960 B

#define MAXFLAG 4096
#define CAND_MAX 64
#define GAP_TAU 5e-3f             // covers 2*err_max of single-pass fp16 (err_max~2e-3)

// top-k candidate machinery
#define CANDN 256
#define BREAK_CNT 160

// fused split kernel partition
#define BT_BLOCKS ((FDIM / 32) * (DDIM / 32))   // 4608
#define A_BLOCKS 1024

// ---- scratch ------------------------------------------------------------------
__device__ float g_h[(size_t)BDIM * FDIM];
__device__ float g_vals[BDIM * KSEL];
__device__ int   g_idx [BDIM * KSEL];
__device__ unsigned g_T[BDIM];
__device__ unsigned g_nflag;
__device__ int   g_flagrows[MAXFLAG];
__device__ __half gAh[(size_t)BDIM * DDIM];
__device__ __half gBh[(size_t)FDIM * DDIM];   // W_inter^T fp16, [n][k]
__device__ float gWT[(size_t)FDIM * DDIM];    // W_inter^T fp32 (coalesced repair dots)

// ---- helpers -------------------------------------------------------------------
__device__ __forceinline__ uint32_t smem_u32(const void* p) {
    uint32_t a;
    asm("{ .reg .u64 t; cvta.to.shared.u64 t, %1; cvt.u32.u64 %0, t; }" : "=r"(a) : "l"(p));
    return a;
}
__device__ __forceinline__ void cp_async16(uint32_t dst, const void* src) {
    asm volatile("cp.async.cg.shared.global [%0], [%1], 16;" :: "r"(dst), "l"(src));
}
__device__ __forceinline__ void ldsm4(uint32_t* r, uint32_t addr) {
    asm volatile("ldmatrix.sync.aligned.m8n8.x4.shared.b16 {%0,%1,%2,%3}, [%4];"
                 : "=r"(r[0]), "=r"(r[1]), "=r"(r[2]), "=r"(r[3]) : "r"(addr));
}
__device__ __forceinline__ void mma16816(float* d, const uint32_t* a, const uint32_t* b) {
    asm volatile("mma.sync.aligned.m16n8k16.row.col.f32.f16.f16.f32 "
                 "{%0,%1,%2,%3}, {%4,%5,%6,%7}, {%8,%9}, {%0,%1,%2,%3};"
                 : "+f"(d[0]), "+f"(d[1]), "+f"(d[2]), "+f"(d[3])
                 : "r"(a[0]), "r"(a[1]), "r"(a[2]), "r"(a[3]), "r"(b[0]), "r"(b[1]));
}

// ---- fused split kernel: fp16 A/W^T + fp32 W^T ----------------------------------
__global__ void __launch_bounds__(256) split_fused(const float* __restrict__ x,
                                                   const float* __restrict__ W)
{
    if (blockIdx.x == 0 && threadIdx.x == 0) g_nflag = 0;

    if (blockIdx.x < BT_BLOCKS) {
        // ---- W^T (32x32 transpose tile): fp16 for MMA + fp32 for repair
        __shared__ float t[32][33];
        const int bid = blockIdx.x;
        const int n0 = (bid % (FDIM / 32)) * 32;
        const int k0 = (bid / (FDIM / 32)) * 32;
        const int tx = threadIdx.x & 31, ty = threadIdx.x >> 5;
#pragma unroll
        for (int i = 0; i < 32; i += 8)
            t[ty + i][tx] = W[(size_t)(k0 + ty + i) * FDIM + n0 + tx];
        __syncthreads();
#pragma unroll
        for (int i = 0; i < 32; i += 8) {
            float v = t[tx][ty + i];
            size_t o = (size_t)(n0 + ty + i) * DDIM + k0 + tx;
            gBh[o] = __float2half_rn(v);
            gWT[o] = v;
        }
    } else {
        // ---- A fp16 (contiguous chunks)
        const size_t n = (size_t)BDIM * DDIM;
        const unsigned aid = blockIdx.x - BT_BLOCKS;
        for (size_t i = (size_t)aid * 256 + threadIdx.x; i < n;
             i += (size_t)A_BLOCKS * 256) {
            gAh[i] = __float2half_rn(x[i]);
        }
    }
}

// ---- tensor-core GEMM: h ~= relu(x @ W + b), single fp16 pass ----------------------
__device__ __forceinline__ void load_tiles(uint32_t sbase, int buf, int ch,
                                           int bm, int bn, int tid)
{
    const uint32_t bb = sbase + buf * BUFB;
    const int k0 = ch * KC2;
    const __half* srcs[2] = { gAh, gBh };
#pragma unroll
    for (int t = 0; t < 2; t++) {
        const int rbase = (t == 0) ? bm : bn;
        const __half* sp = srcs[t] + (size_t)rbase * DDIM + k0;
        const uint32_t tb = bb + t * TILEB;
#pragma unroll
        for (int i = tid; i < 512; i += 256) {
            const int row = i >> 2, seg = i & 3;
            cp_async16(tb + row * ROWBYTES + seg * 16, sp + (size_t)row * DDIM + seg * 8);
        }
    }
    asm volatile("cp.async.commit_group;" ::: "memory");
}

__global__ void __launch_bounds__(256, 1) mma_gemm(const float* __restrict__ bias)
{
    extern __shared__ char dsm[];
    const uint32_t sbase = smem_u32(dsm);
    const int tid = threadIdx.x, wid = tid >> 5, lane = tid & 31;
    const int bm = blockIdx.y * 128, bn = blockIdx.x * 128;
    const int wm = (wid >> 2) * 64;
    const int wn = (wid & 3) * 32;

    float d[4][4][4];
#pragma unroll
    for (int i = 0; i < 4; i++)
#pragma unroll
        for (int j = 0; j < 4; j++)
#pragma unroll
            for (int q = 0; q < 4; q++) d[i][j][q] = 0.f;

    load_tiles(sbase, 0, 0, bm, bn, tid);
    load_tiles(sbase, 1, 1, bm, bn, tid);

    const uint32_t aoff = (uint32_t)(wm + (lane & 15)) * ROWBYTES + ((lane >> 4) * 8) * 2;
    const uint32_t boff = (uint32_t)(wn + ((lane >> 4) & 1) * 8 + (lane & 7)) * ROWBYTES
                        + (((lane >> 3) & 1) * 8) * 2;

#pragma unroll 1
    for (int ch = 0; ch < NCH; ch++) {
        const int buf = ch & 1;
        if (ch < NCH - 1) asm volatile("cp.async.wait_group 1;" ::: "memory");
        else              asm volatile("cp.async.wait_group 0;" ::: "memory");
        __syncthreads();

        const uint32_t bb = sbase + buf * BUFB;
#pragma unroll
        for (int kk = 0; kk < 2; kk++) {
            const uint32_t ko = kk * 32;
            uint32_t ah[4][4], bh[2][4];
#pragma unroll
            for (int ma = 0; ma < 4; ma++)
                ldsm4(ah[ma], bb + aoff + ma * 16 * ROWBYTES + ko);
#pragma unroll
            for (int pr = 0; pr < 2; pr++)
                ldsm4(bh[pr], bb + TILEB + boff + pr * 16 * ROWBYTES + ko);
#pragma unroll
            for (int ma = 0; ma < 4; ma++)
#pragma unroll
                for (int na = 0; na < 4; na++)
                    mma16816(d[ma][na], ah[ma], &bh[na >> 1][(na & 1) * 2]);
        }
        __syncthreads();
        if (ch + 2 < NCH) load_tiles(sbase, buf, ch + 2, bm, bn, tid);
    }

#pragma unroll
    for (int na = 0; na < 4; na++) {
        const int n0g = bn + wn + na * 8 + (lane & 3) * 2;
        const float b0 = bias[n0g], b1 = bias[n0g + 1];
#pragma unroll
        for (int ma = 0; ma < 4; ma++) {
            const int m0g = bm + wm + ma * 16 + (lane >> 2);
            float v0 = __fadd_rn(d[ma][na][0], b0);
            float v1 = __fadd_rn(d[ma][na][1], b1);
            float v2 = __fadd_rn(d[ma][na][2], b0);
            float v3 = __fadd_rn(d[ma][na][3], b1);
            float2 o0 = { (v0 > 0.f) ? v0 : 0.f, (v1 > 0.f) ? v1 : 0.f };
            float2 o1 = { (v2 > 0.f) ? v2 : 0.f, (v3 > 0.f) ? v3 : 0.f };
            *(float2*)&g_h[(size_t)m0g * FDIM + n0g]       = o0;
            *(float2*)&g_h[(size_t)(m0g + 8) * FDIM + n0g] = o1;
        }
    }
}

// ---- top-64: truncated bitwise search + exact candidate ranking -------------------
__global__ void __launch_bounds__(256) topk_kernel(float* __restrict__ sparse)
{
    const int row = blockIdx.x;
    const int tid = threadIdx.x;
    const int lane = tid & 31, wid = tid >> 5;

    __shared__ unsigned warpcnt[2][8];
    __shared__ unsigned warpmax[8];
    __shared__ unsigned cu[CANDN];
    __shared__ int      ci[CANDN];
    __shared__ unsigned s_T64, s_v65;

    const float* hrow = g_h + (size_t)row * FDIM;
    uint4 vb[6];
#pragma unroll
    for (int q = 0; q < 6; q++)
        vb[q] = ((const uint4*)hrow)[q * 256 + tid];

    if (tid == 0) { s_T64 = 0u; s_v65 = 0u; }

    // ---- phase 1: truncated greedy bit search
    unsigned T = 0, curcnt = FDIM;
#pragma unroll 1
    for (int b = 30; b >= 0; --b) {
        const unsigned cand = T | (1u << b);
        unsigned lc = 0;
#pragma unroll
        for (int q = 0; q < 6; q++) {
            lc += (vb[q].x >= cand) + (vb[q].y >= cand)
                + (vb[q].z >= cand) + (vb[q].w >= cand);
        }
        lc = __reduce_add_sync(0xFFFFFFFFu, lc);
        const int pb = b & 1;
        if (lane == 0) warpcnt[pb][wid] = lc;
        __syncthreads();
        unsigned cnt = 0;
#pragma unroll
        for (int w = 0; w < 8; w++) cnt += warpcnt[pb][w];
        if (cnt >= KSEL) { T = cand; curcnt = cnt; }
        if (curcnt <= BREAK_CNT) break;
    }
    __syncthreads();

    // ---- phase 2: atomic-free ballot compaction of candidates {u >= T}
    unsigned wcnt = 0;
#pragma unroll
    for (int q = 0; q < 6; q++) {
        unsigned u[4] = { vb[q].x, vb[q].y, vb[q].z, vb[q].w };
#pragma unroll
        for (int c = 0; c < 4; c++)
            wcnt += __popc(__ballot_sync(0xFFFFFFFFu, u[c] >= T));
    }
    if (lane == 0) warpcnt[0][wid] = wcnt;
    __syncthreads();
    unsigned nc = 0, wbase = 0;
#pragma unroll
    for (int w = 0; w < 8; w++) {
        if (w < wid) wbase += warpcnt[0][w];
        nc += warpcnt[0][w];
    }
    if (nc > CANDN) nc = CANDN;
    {
        unsigned base = wbase;
        const unsigned ltmask = (1u << lane) - 1u;
#pragma unroll
        for (int q = 0; q < 6; q++) {
            const int c0 = q * 1024 + tid * 4;
            unsigned u[4] = { vb[q].x, vb[q].y, vb[q].z, vb[q].w };
#pragma unroll
            for (int c = 0; c < 4; c++) {
                const bool pred = (u[c] >= T);
                const unsigned m = __ballot_sync(0xFFFFFFFFu, pred);
                if (pred) {
                    unsigned slot = base + __popc(m & ltmask);
                    if (slot < CANDN) { cu[slot] = u[c]; ci[slot] = c0 + c; }
                }
                base += __popc(m);
            }
        }
    }
    __syncthreads();

    // ---- phase 3: exact rank (value desc, index asc) over candidates
    float* vrow = g_vals + row * KSEL;
    int*   irow = g_idx  + row * KSEL;
    for (unsigned j = tid; j < nc; j += 256) {
        const unsigned v = cu[j];
        const int id = ci[j];
        int r = 0;
        for (unsigned m = 0; m < nc; m++) {
            const unsigned w = cu[m];
            r += (w > v) || (w == v && ci[m] < id);
        }
        if (r < KSEL) { vrow[r] = __uint_as_float(v); irow[r] = id; }
        if (r == KSEL - 1) s_T64 = v;
        if (r == KSEL)     s_v65 = v;
    }
    __syncthreads();
    const unsigned T64 = s_T64;

    // ---- phase 4: write sparse, track non-candidate max
    float* srow = sparse + (size_t)row * FDIM;
    unsigned bmax = 0;
#pragma unroll
    for (int q = 0; q < 6; q++) {
        const int c0 = q * 1024 + tid * 4;
        unsigned u[4] = { vb[q].x, vb[q].y, vb[q].z, vb[q].w };
        float o[4];
#pragma unroll
        for (int c = 0; c < 4; c++) {
            o[c] = (u[c] > T64) ? __uint_as_float(u[c]) : 0.f;
            if (u[c] < T) bmax = max(bmax, u[c]);
        }
        *(float4*)&srow[c0] = *(const float4*)o;
    }
#pragma unroll
    for (int o2 = 16; o2; o2 >>= 1) bmax = max(bmax, __shfl_xor_sync(0xFFFFFFFFu, bmax, o2));
    if (lane == 0) warpmax[wid] = bmax;
    __syncthreads();

    if (tid < KSEL) srow[irow[tid]] = vrow[tid];

    if (tid == 0) {
        unsigned below;
        if (nc > KSEL) below = s_v65;
        else {
            below = 0;
#pragma unroll
            for (int w = 0; w < 8; w++) below = max(below, warpmax[w]);
        }
        g_T[row] = T64;
        const float gap = __uint_as_float(T64) - __uint_as_float(below);
        if (T64 != 0u && gap < GAP_TAU) {
            unsigned p = atomicAdd(&g_nflag, 1u);
            if (p < MAXFLAG) g_flagrows[p] = row;
        }
    }
}

// ---- exact repair of flagged rows: coalesced W^T dots, warp-per-candidate ----------
__global__ void __launch_bounds__(256) repair_kernel(
    const float* __restrict__ x, const float* __restrict__ bi,
    float* __restrict__ sparse)
{
    __shared__ float xs[DDIM];
    __shared__ int   cand[CAND_MAX];
    __shared__ float cex[CAND_MAX];
    __shared__ unsigned s_nc, s_nhi;

    unsigned nf = min(g_nflag, (unsigned)MAXFLAG);
    if (blockIdx.x >= nf) return;
    const int row = g_flagrows[blockIdx.x];
    const int tid = threadIdx.x;
    const int wid = tid >> 5, lane = tid & 31;
    const float Tval = __uint_as_float(g_T[row]);
    const float* hrow = g_h + (size_t)row * FDIM;

    for (int i = tid; i < DDIM; i += 256) xs[i] = x[(size_t)row * DDIM + i];
    if (tid == 0) { s_nc = 0; s_nhi = 0; }
    __syncthreads();

    unsigned nhi_loc = 0;
    for (int f = tid; f < FDIM; f += 256) {
        float v = hrow[f];
        if (fabsf(v - Tval) <= GAP_TAU) {
            unsigned p = atomicAdd(&s_nc, 1u);
            if (p < CAND_MAX) cand[p] = f;
        } else if (v > Tval) nhi_loc++;
    }
    atomicAdd(&s_nhi, nhi_loc);
    __syncthreads();
    const unsigned nc = s_nc;
    if (nc > CAND_MAX) return;   // statistically impossible

    // warp-per-candidate exact fp32 dots over contiguous gWT columns
    for (unsigned j = wid; j < nc; j += 8) {
        const float* wcol = gWT + (size_t)cand[j] * DDIM;
        float s = 0.f, c = 0.f;
        for (int d = lane; d < DDIM; d += 32) {
            float p = __fmaf_rn(xs[d], wcol[d], 0.f);
            float y = __fsub_rn(p, c);
            float t2 = __fadd_rn(s, y);
            c = __fsub_rn(__fsub_rn(t2, s), y);
            s = t2;
        }
#pragma unroll
        for (int o = 16; o; o >>= 1) s = __fadd_rn(s, __shfl_xor_sync(0xFFFFFFFFu, s, o));
        if (lane == 0) {
            float v = __fadd_rn(s, bi[cand[j]]);
            cex[j] = (v > 0.f) ? v : 0.f;
        }
    }
    __syncthreads();
    if (tid != 0) return;

    float* srow = sparse + (size_t)row * FDIM;
    float* vrow = g_vals + row * KSEL;
    int*   irow = g_idx  + row * KSEL;

    int k_rem = KSEL - (int)s_nhi;
    bool want[CAND_MAX], cur[CAND_MAX];
    for (unsigned j = 0; j < nc; j++) {
        want[j] = false;
        cur[j] = (srow[cand[j]] != 0.f);
    }
    for (int slot = 0; slot < k_rem; slot++) {
        int best = -1;
        for (unsigned j = 0; j < nc; j++) {
            if (want[j]) continue;
            if (best < 0 || cex[j] > cex[best] ||
                (cex[j] == cex[best] && cand[j] < cand[best])) best = (int)j;
        }
        if (best >= 0) want[best] = true;
    }
    int addq[CAND_MAX]; int na = 0;
    for (unsigned j = 0; j < nc; j++) if (want[j] && !cur[j]) addq[na++] = (int)j;
    int ai = 0;
    for (unsigned j = 0; j < nc && ai < na; j++) {
        if (cur[j] && !want[j]) {
            int rf = cand[j];
            int af = cand[addq[ai]]; ai++;
            float av = hrow[af];
            srow[rf] = 0.f;
            srow[af] = av;
            for (int q = 0; q < KSEL; q++)
                if (irow[q] == rf) { irow[q] = af; vrow[q] = av; break; }
        }
    }
}

// ---- classifier (fp32 gather — proven) -------------------------------------------
__global__ void __launch_bounds__(256) cls_kernel(
    const float* __restrict__ Wc, const float* __restrict__ bc,
    float* __restrict__ logits)
{
    const int row = blockIdx.x;
    const int tid = threadIdx.x;
    __shared__ float sv[KSEL];
    __shared__ int   si[KSEL];
    if (tid < KSEL) {
        sv[tid] = g_vals[row * KSEL + tid];
        si[tid] = g_idx [row * KSEL + tid];
    }
    __syncthreads();
    if (tid >= 250) return;
    const int c = tid * 4;
    float4 acc = *(const float4*)&bc[c];
#pragma unroll 4
    for (int j = 0; j < KSEL; j++) {
        const float v = sv[j];
        const float4 w = *(const float4*)&Wc[(size_t)si[j] * CDIM + c];
        acc.x = fmaf(v, w.x, acc.x);
        acc.y = fmaf(v, w.y, acc.y);
        acc.z = fmaf(v, w.z, acc.z);
        acc.w = fmaf(v, w.w, acc.w);
    }
    *(float4*)&logits[(size_t)row * CDIM + c] = acc;
}

// ----------------------------------------------------------------------------------------
extern "C" void kernel_launch(void* const* d_in, const int* in_sizes, int n_in,
                              void* d_out, int out_size)
{
    const float* x  = (const float*)d_in[0];
    const float* Wi = (const float*)d_in[1];
    const float* bi = (const float*)d_in[2];
    const float* Wc = (const float*)d_in[3];
    const float* bc = (const float*)d_in[4];
    (void)in_sizes; (void)n_in; (void)out_size;

    float* sparse = (float*)d_out;
    float* logits = (float*)d_out + (size_t)BDIM * FDIM;

    static int smem_set = 0;
    if (!smem_set) {
        cudaFuncSetAttribute(mma_gemm, cudaFuncAttributeMaxDynamicSharedMemorySize, SMEMDYN);
        smem_set = 1;
    }

    split_fused<<<BT_BLOCKS + A_BLOCKS, 256>>>(x, Wi);
    mma_gemm<<<dim3(FDIM / 128, BDIM / 128), 256, SMEMDYN>>>(bi);
    topk_kernel<<<BDIM, 256>>>(sparse);
    repair_kernel<<<MAXFLAG, 256>>>(x, bi, sparse);
    cls_kernel<<<BDIM, 256>>>(Wc, bc, logits);
}